// round 1
// baseline (speedup 1.0000x reference)
#include <cuda_runtime.h>
#include <math.h>
#include <stdint.h>

// ---------------- problem-size constants (static scratch sizing) ----------------
#define NMAX 100000
#define EMAX 1600000

// ---------------- device scratch (allocation-free rule: __device__ globals) ------
__device__ float g_xi[(size_t)NMAX * 128];      // x @ W_aff^T + b_aff
__device__ float g_gh[(size_t)NMAX * 384];      // x @ W_hh^T + b_hh
__device__ float g_gi[(size_t)NMAX * 384];      // agg_max @ W_ih^T + b_ih
__device__ float g_aggmax[(size_t)NMAX * 128];  // segment-max (post isfinite fix)
__device__ float g_cat[(size_t)NMAX * 256];     // [agg_sum | rnn_out]
__device__ float g_h[(size_t)NMAX * 128];       // merge output (+ eps*x)
__device__ float g_t[(size_t)NMAX * 256];       // relu(h @ W1^T + b1)

__device__ int g_cnt[NMAX];        // in-degree
__device__ int g_rowstart[NMAX];   // CSR row starts (exclusive scan of cnt)
__device__ int g_cursor[NMAX];     // fill cursors
__device__ int g_col[EMAX];        // CSR neighbor (src) list
__device__ int g_bsum[256];        // scan block sums
__device__ int g_boff[256];        // scan block offsets
__device__ float g_bnsum[128];     // batchnorm column sums
__device__ float g_bnsq[128];      // batchnorm column sum-of-squares

// ---------------- init ----------------
__global__ void zero_init_kernel(int n) {
    int i = blockIdx.x * blockDim.x + threadIdx.x;
    if (i < n) g_cnt[i] = 0;
    if (i < 128) { g_bnsum[i] = 0.f; g_bnsq[i] = 0.f; }
}

// ---------------- CSR build: count, scan, fill ----------------
__global__ void count_kernel(const int* __restrict__ edges, int E) {
    int e = blockIdx.x * blockDim.x + threadIdx.x;
    if (e >= E) return;
    atomicAdd(&g_cnt[edges[E + e]], 1);  // edges[1][e] = dst
}

__global__ void scan1_kernel(int n) {
    __shared__ int sh[1024];
    int tid = threadIdx.x;
    int i = blockIdx.x * 1024 + tid;
    int v = (i < n) ? g_cnt[i] : 0;
    sh[tid] = v;
    __syncthreads();
    for (int off = 1; off < 1024; off <<= 1) {
        int t = (tid >= off) ? sh[tid - off] : 0;
        __syncthreads();
        sh[tid] += t;
        __syncthreads();
    }
    if (i < n) g_rowstart[i] = sh[tid] - v;  // exclusive within block
    if (tid == 1023) g_bsum[blockIdx.x] = sh[1023];
}

__global__ void scan2_kernel(int nb) {
    if (threadIdx.x == 0) {
        int run = 0;
        for (int i = 0; i < nb; i++) { int t = g_bsum[i]; g_boff[i] = run; run += t; }
    }
}

__global__ void scan3_kernel(int n) {
    int i = blockIdx.x * blockDim.x + threadIdx.x;
    if (i < n) {
        int v = g_rowstart[i] + g_boff[i >> 10];
        g_rowstart[i] = v;
        g_cursor[i] = v;
    }
}

__global__ void fill_kernel(const int* __restrict__ edges, int E) {
    int e = blockIdx.x * blockDim.x + threadIdx.x;
    if (e >= E) return;
    int src = edges[e];
    int dst = edges[E + e];
    int pos = atomicAdd(&g_cursor[dst], 1);
    g_col[pos] = src;
}

// ---------------- SGEMM: C[M,N] = act(A[M,K] @ B[N,K]^T + bias [+ eps*resid]) ----
// 128x128 block tile, BK=16, 256 threads, 8x8 per-thread tile.
// N must be a multiple of 128 (all call sites: 128/256/384).
__global__ __launch_bounds__(256) void sgemm_kernel(
    const float* __restrict__ A, const float* __restrict__ B,
    const float* __restrict__ bias, float* __restrict__ C,
    int M, int N, int K, int relu,
    const float* __restrict__ resid, const float* __restrict__ eps_ptr)
{
    __shared__ float As[16][132];
    __shared__ float Bs[16][132];
    int tid = threadIdx.x;
    int tx = tid & 15, ty = tid >> 4;
    int bm = blockIdx.y * 128, bn = blockIdx.x * 128;

    float acc[8][8];
#pragma unroll
    for (int i = 0; i < 8; i++)
#pragma unroll
        for (int j = 0; j < 8; j++) acc[i][j] = 0.f;

    for (int k0 = 0; k0 < K; k0 += 16) {
#pragma unroll
        for (int l = 0; l < 2; l++) {
            int f = tid + l * 256;
            int row = f >> 2, kq = f & 3;
            int gr = bm + row; if (gr >= M) gr = M - 1;  // stores are guarded
            float4 v = *(const float4*)(A + (size_t)gr * K + (k0 + kq * 4));
            As[kq * 4 + 0][row] = v.x; As[kq * 4 + 1][row] = v.y;
            As[kq * 4 + 2][row] = v.z; As[kq * 4 + 3][row] = v.w;
        }
#pragma unroll
        for (int l = 0; l < 2; l++) {
            int f = tid + l * 256;
            int row = f >> 2, kq = f & 3;
            float4 v = *(const float4*)(B + (size_t)(bn + row) * K + (k0 + kq * 4));
            Bs[kq * 4 + 0][row] = v.x; Bs[kq * 4 + 1][row] = v.y;
            Bs[kq * 4 + 2][row] = v.z; Bs[kq * 4 + 3][row] = v.w;
        }
        __syncthreads();
#pragma unroll
        for (int k = 0; k < 16; k++) {
            float a[8], b[8];
            *(float4*)(a)     = *(const float4*)&As[k][ty * 8];
            *(float4*)(a + 4) = *(const float4*)&As[k][ty * 8 + 4];
            *(float4*)(b)     = *(const float4*)&Bs[k][tx * 8];
            *(float4*)(b + 4) = *(const float4*)&Bs[k][tx * 8 + 4];
#pragma unroll
            for (int i = 0; i < 8; i++)
#pragma unroll
                for (int j = 0; j < 8; j++)
                    acc[i][j] = fmaf(a[i], b[j], acc[i][j]);
        }
        __syncthreads();
    }

    float e = 0.f;
    if (resid) e = *eps_ptr;
#pragma unroll
    for (int i = 0; i < 8; i++) {
        int gr = bm + ty * 8 + i;
        if (gr >= M) continue;
#pragma unroll
        for (int jq = 0; jq < 2; jq++) {
            int gc = bn + tx * 8 + jq * 4;
            float4 bv = *(const float4*)(bias + gc);
            float4 o;
            o.x = acc[i][jq * 4 + 0] + bv.x;
            o.y = acc[i][jq * 4 + 1] + bv.y;
            o.z = acc[i][jq * 4 + 2] + bv.z;
            o.w = acc[i][jq * 4 + 3] + bv.w;
            if (resid) {
                float4 rv = *(const float4*)(resid + (size_t)gr * N + gc);
                o.x += e * rv.x; o.y += e * rv.y; o.z += e * rv.z; o.w += e * rv.w;
            }
            if (relu) {
                o.x = fmaxf(o.x, 0.f); o.y = fmaxf(o.y, 0.f);
                o.z = fmaxf(o.z, 0.f); o.w = fmaxf(o.w, 0.f);
            }
            *(float4*)(C + (size_t)gr * N + gc) = o;
        }
    }
}

// ---------------- warp-per-node gather + segment sum/max ----------------
__global__ void gather_reduce_kernel(const float* __restrict__ x, int n) {
    int gt = blockIdx.x * blockDim.x + threadIdx.x;
    int node = gt >> 5;
    if (node >= n) return;
    int lane = gt & 31;
    int start = g_rowstart[node];
    int deg = g_cnt[node];
    float4 s = make_float4(0.f, 0.f, 0.f, 0.f);
    float4 m = make_float4(-1e30f, -1e30f, -1e30f, -1e30f);
    int j = 0;
    for (; j + 2 <= deg; j += 2) {
        int nb0 = g_col[start + j], nb1 = g_col[start + j + 1];
        float4 x0 = __ldg((const float4*)(x + (size_t)nb0 * 128 + lane * 4));
        float4 x1 = __ldg((const float4*)(x + (size_t)nb1 * 128 + lane * 4));
        float4 i0 = __ldg((const float4*)(g_xi + (size_t)nb0 * 128 + lane * 4));
        float4 i1 = __ldg((const float4*)(g_xi + (size_t)nb1 * 128 + lane * 4));
        s.x += x0.x + x1.x; s.y += x0.y + x1.y; s.z += x0.z + x1.z; s.w += x0.w + x1.w;
        m.x = fmaxf(m.x, fmaxf(i0.x, i1.x)); m.y = fmaxf(m.y, fmaxf(i0.y, i1.y));
        m.z = fmaxf(m.z, fmaxf(i0.z, i1.z)); m.w = fmaxf(m.w, fmaxf(i0.w, i1.w));
    }
    if (j < deg) {
        int nb = g_col[start + j];
        float4 xv = __ldg((const float4*)(x + (size_t)nb * 128 + lane * 4));
        float4 iv = __ldg((const float4*)(g_xi + (size_t)nb * 128 + lane * 4));
        s.x += xv.x; s.y += xv.y; s.z += xv.z; s.w += xv.w;
        m.x = fmaxf(m.x, iv.x); m.y = fmaxf(m.y, iv.y);
        m.z = fmaxf(m.z, iv.z); m.w = fmaxf(m.w, iv.w);
    }
    if (deg == 0) m = make_float4(0.f, 0.f, 0.f, 0.f);  // empty segment -> 0 (isfinite fix)
    *(float4*)(g_cat + (size_t)node * 256 + lane * 4) = s;      // agg_sum -> cat[:, :128]
    *(float4*)(g_aggmax + (size_t)node * 128 + lane * 4) = m;
}

// ---------------- GRU cell elementwise ----------------
__device__ __forceinline__ float gru1(float ir, float hr, float iz, float hz,
                                      float inn, float hn, float xv) {
    float r = 1.f / (1.f + expf(-(ir + hr)));
    float z = 1.f / (1.f + expf(-(iz + hz)));
    float nc = tanhf(inn + r * hn);
    return (1.f - z) * nc + z * xv;
}

__global__ void gru_kernel(const float* __restrict__ x, int M) {
    int idx = blockIdx.x * blockDim.x + threadIdx.x;
    if (idx >= M * 32) return;
    int node = idx >> 5;
    int c = (idx & 31) * 4;
    const float* gi = g_gi + (size_t)node * 384;
    const float* gh = g_gh + (size_t)node * 384;
    float4 ir = *(const float4*)(gi + c);
    float4 iz = *(const float4*)(gi + 128 + c);
    float4 in = *(const float4*)(gi + 256 + c);
    float4 hr = *(const float4*)(gh + c);
    float4 hz = *(const float4*)(gh + 128 + c);
    float4 hn = *(const float4*)(gh + 256 + c);
    float4 xv = *(const float4*)(x + (size_t)node * 128 + c);
    float4 o;
    o.x = gru1(ir.x, hr.x, iz.x, hz.x, in.x, hn.x, xv.x);
    o.y = gru1(ir.y, hr.y, iz.y, hz.y, in.y, hn.y, xv.y);
    o.z = gru1(ir.z, hr.z, iz.z, hz.z, in.z, hn.z, xv.z);
    o.w = gru1(ir.w, hr.w, iz.w, hz.w, in.w, hn.w, xv.w);
    *(float4*)(g_cat + (size_t)node * 256 + 128 + c) = o;       // rnn_out -> cat[:, 128:]
}

// ---------------- batchnorm ----------------
__global__ void bn_reduce_kernel(const float* __restrict__ h2, int M, int chunk) {
    int c = threadIdx.x;  // 128 threads = 128 columns
    int r0 = blockIdx.x * chunk;
    int r1 = min(r0 + chunk, M);
    float s = 0.f, q = 0.f;
    for (int r = r0; r < r1; r++) {
        float v = h2[(size_t)r * 128 + c];
        s += v; q += v * v;
    }
    atomicAdd(&g_bnsum[c], s);
    atomicAdd(&g_bnsq[c], q);
}

__global__ void bn_norm_kernel(float* __restrict__ out, const float* __restrict__ gamma,
                               const float* __restrict__ beta, int M, float invM) {
    int idx = blockIdx.x * blockDim.x + threadIdx.x;
    if (idx >= M * 32) return;
    int node = idx >> 5;
    int c = (idx & 31) * 4;
    float4 v = *(float4*)(out + (size_t)node * 128 + c);
    float4 sm = *(const float4*)(g_bnsum + c);
    float4 sq = *(const float4*)(g_bnsq + c);
    float4 gm = *(const float4*)(gamma + c);
    float4 bt = *(const float4*)(beta + c);
    float4 o;
    {
        float mean = sm.x * invM, var = sq.x * invM - mean * mean;
        o.x = gm.x * (v.x - mean) * rsqrtf(var + 1e-5f) + bt.x;
    }
    {
        float mean = sm.y * invM, var = sq.y * invM - mean * mean;
        o.y = gm.y * (v.y - mean) * rsqrtf(var + 1e-5f) + bt.y;
    }
    {
        float mean = sm.z * invM, var = sq.z * invM - mean * mean;
        o.z = gm.z * (v.z - mean) * rsqrtf(var + 1e-5f) + bt.z;
    }
    {
        float mean = sm.w * invM, var = sq.w * invM - mean * mean;
        o.w = gm.w * (v.w - mean) * rsqrtf(var + 1e-5f) + bt.w;
    }
    *(float4*)(out + (size_t)node * 128 + c) = o;
}

// ---------------- launch ----------------
extern "C" void kernel_launch(void* const* d_in, const int* in_sizes, int n_in,
                              void* d_out, int out_size) {
    const float* x       = (const float*)d_in[0];
    const int*   edges   = (const int*)d_in[1];
    const float* W_aff   = (const float*)d_in[2];
    const float* b_aff   = (const float*)d_in[3];
    const float* W_ih    = (const float*)d_in[4];
    const float* b_ih    = (const float*)d_in[5];
    const float* W_hh    = (const float*)d_in[6];
    const float* b_hh    = (const float*)d_in[7];
    const float* W_merge = (const float*)d_in[8];
    const float* b_merge = (const float*)d_in[9];
    const float* eps     = (const float*)d_in[10];
    const float* W1      = (const float*)d_in[11];
    const float* b1      = (const float*)d_in[12];
    const float* W2      = (const float*)d_in[13];
    const float* b2      = (const float*)d_in[14];
    const float* gamma   = (const float*)d_in[15];
    const float* beta    = (const float*)d_in[16];
    float* out = (float*)d_out;

    int M = in_sizes[0] / 128;   // 100000 nodes
    int E = in_sizes[1] / 2;     // 1600000 edges

    float *p_xi, *p_gh, *p_gi, *p_aggmax, *p_cat, *p_h, *p_t;
    cudaGetSymbolAddress((void**)&p_xi, g_xi);
    cudaGetSymbolAddress((void**)&p_gh, g_gh);
    cudaGetSymbolAddress((void**)&p_gi, g_gi);
    cudaGetSymbolAddress((void**)&p_aggmax, g_aggmax);
    cudaGetSymbolAddress((void**)&p_cat, g_cat);
    cudaGetSymbolAddress((void**)&p_h, g_h);
    cudaGetSymbolAddress((void**)&p_t, g_t);

    // CSR build
    zero_init_kernel<<<(M + 255) / 256, 256>>>(M);
    count_kernel<<<(E + 255) / 256, 256>>>(edges, E);
    int nb = (M + 1023) / 1024;
    scan1_kernel<<<nb, 1024>>>(M);
    scan2_kernel<<<1, 32>>>(nb);
    scan3_kernel<<<(M + 255) / 256, 256>>>(M);
    fill_kernel<<<(E + 255) / 256, 256>>>(edges, E);

    int mb = (M + 127) / 128;

    // xi = x @ W_aff^T + b_aff ;  gh = x @ W_hh^T + b_hh
    sgemm_kernel<<<dim3(1, mb), 256>>>(x, W_aff, b_aff, p_xi, M, 128, 128, 0, nullptr, nullptr);
    sgemm_kernel<<<dim3(3, mb), 256>>>(x, W_hh, b_hh, p_gh, M, 384, 128, 0, nullptr, nullptr);

    // segment sum(x) and max(xi)
    gather_reduce_kernel<<<(M * 32 + 255) / 256, 256>>>(x, M);

    // gi = agg_max @ W_ih^T + b_ih
    sgemm_kernel<<<dim3(3, mb), 256>>>(p_aggmax, W_ih, b_ih, p_gi, M, 384, 128, 0, nullptr, nullptr);

    // GRU -> cat[:,128:]
    gru_kernel<<<(M * 32 + 255) / 256, 256>>>(x, M);

    // h = cat @ W_merge^T + b_merge + eps*x
    sgemm_kernel<<<dim3(1, mb), 256>>>(p_cat, W_merge, b_merge, p_h, M, 128, 256, 0, x, eps);

    // t = relu(h @ W1^T + b1) ; h2 = relu(t @ W2^T + b2) -> d_out
    sgemm_kernel<<<dim3(2, mb), 256>>>(p_h, W1, b1, p_t, M, 256, 128, 1, nullptr, nullptr);
    sgemm_kernel<<<dim3(1, mb), 256>>>(p_t, W2, b2, out, M, 128, 256, 1, nullptr, nullptr);

    // batchnorm (train mode, biased variance)
    int chunk = (M + 1023) / 1024;
    bn_reduce_kernel<<<1024, 128>>>(out, M, chunk);
    bn_norm_kernel<<<(M * 32 + 255) / 256, 256>>>(out, gamma, beta, M, 1.0f / (float)M);
}

// round 3
// speedup vs baseline: 1.6497x; 1.6497x over previous
#include <cuda_runtime.h>
#include <cuda_bf16.h>
#include <math.h>
#include <stdint.h>

// ---------------- problem-size constants ----------------
#define NMAX 100000
#define EMAX 1600000

// ---------------- device scratch ----------------
__device__ float g_xi[(size_t)NMAX * 128];   // fp32: x @ W_aff^T + b_aff (gather reads it)
__device__ float g_gh[(size_t)NMAX * 384];   // fp32: x @ W_hh^T + b_hh  (GRU reads)
__device__ float g_gi[(size_t)NMAX * 384];   // fp32: agg_max @ W_ih^T + b_ih (GRU reads)

__device__ __align__(16) __nv_bfloat16 g_x_h[(size_t)NMAX * 128];
__device__ __align__(16) __nv_bfloat16 g_x_l[(size_t)NMAX * 128];
__device__ __align__(16) __nv_bfloat16 g_am_h[(size_t)NMAX * 128];
__device__ __align__(16) __nv_bfloat16 g_am_l[(size_t)NMAX * 128];
__device__ __align__(16) __nv_bfloat16 g_cat_h[(size_t)NMAX * 256];
__device__ __align__(16) __nv_bfloat16 g_cat_l[(size_t)NMAX * 256];
__device__ __align__(16) __nv_bfloat16 g_hh_h[(size_t)NMAX * 128];
__device__ __align__(16) __nv_bfloat16 g_hh_l[(size_t)NMAX * 128];
__device__ __align__(16) __nv_bfloat16 g_t_h[(size_t)NMAX * 256];
__device__ __align__(16) __nv_bfloat16 g_t_l[(size_t)NMAX * 256];
__device__ __align__(16) __nv_bfloat16 g_w_h[262144];
__device__ __align__(16) __nv_bfloat16 g_w_l[262144];

__device__ int g_cnt[NMAX];
__device__ int g_rowstart[NMAX];
__device__ int g_cursor[NMAX];
__device__ int g_col[EMAX];
__device__ int g_bsum[256];
__device__ int g_boff[256];
__device__ float g_bnsum[128];
__device__ float g_bnsq[128];

// weight offsets within g_w_h / g_w_l
#define OFF_AFF 0
#define OFF_IH  16384
#define OFF_HH  65536
#define OFF_MG  114688
#define OFF_W1  147456
#define OFF_W2  180224

// ---------------- low-level helpers (all plain sm_80-class PTX) ----------------
__device__ __forceinline__ uint32_t smem_u32(const void* p) {
    uint32_t a;
    asm("{ .reg .u64 t; cvta.to.shared.u64 t, %1; cvt.u32.u64 %0, t; }" : "=r"(a) : "l"(p));
    return a;
}
__device__ __forceinline__ void cpasync16(uint32_t dst, const void* src) {
    asm volatile("cp.async.cg.shared.global [%0], [%1], 16;" :: "r"(dst), "l"(src));
}
__device__ __forceinline__ void cp_commit() {
    asm volatile("cp.async.commit_group;" ::: "memory");
}
__device__ __forceinline__ void cp_wait1() {
    asm volatile("cp.async.wait_group 1;" ::: "memory");
}
__device__ __forceinline__ void cp_wait0() {
    asm volatile("cp.async.wait_group 0;" ::: "memory");
}
__device__ __forceinline__ void ldsm4(uint32_t* r, uint32_t addr) {
    asm volatile("ldmatrix.sync.aligned.m8n8.x4.shared.b16 {%0,%1,%2,%3}, [%4];"
                 : "=r"(r[0]), "=r"(r[1]), "=r"(r[2]), "=r"(r[3]) : "r"(addr));
}
__device__ __forceinline__ void mma_bf16(float* d, const uint32_t* a, const uint32_t* b) {
    asm volatile(
        "mma.sync.aligned.m16n8k16.row.col.f32.bf16.bf16.f32 "
        "{%0,%1,%2,%3}, {%4,%5,%6,%7}, {%8,%9}, {%0,%1,%2,%3};"
        : "+f"(d[0]), "+f"(d[1]), "+f"(d[2]), "+f"(d[3])
        : "r"(a[0]), "r"(a[1]), "r"(a[2]), "r"(a[3]), "r"(b[0]), "r"(b[1]));
}

// ---------------- hi/lo bf16 split helpers ----------------
__device__ __forceinline__ void split1(float v, unsigned short& hb, unsigned short& lb) {
    __nv_bfloat16 h = __float2bfloat16(v);
    float hf = __bfloat162float(h);
    __nv_bfloat16 l = __float2bfloat16(v - hf);
    hb = __bfloat16_as_ushort(h);
    lb = __bfloat16_as_ushort(l);
}
__device__ __forceinline__ void split_store4(__nv_bfloat16* ph, __nv_bfloat16* pl, float4 v) {
    unsigned short h0, h1, h2, h3, l0, l1, l2, l3;
    split1(v.x, h0, l0); split1(v.y, h1, l1); split1(v.z, h2, l2); split1(v.w, h3, l3);
    uint2 uh = make_uint2((uint32_t)h0 | ((uint32_t)h1 << 16), (uint32_t)h2 | ((uint32_t)h3 << 16));
    uint2 ul = make_uint2((uint32_t)l0 | ((uint32_t)l1 << 16), (uint32_t)l2 | ((uint32_t)l3 << 16));
    *(uint2*)ph = uh;
    *(uint2*)pl = ul;
}
__device__ __forceinline__ void split_store2(__nv_bfloat16* ph, __nv_bfloat16* pl, float a, float b) {
    unsigned short h0, h1, l0, l1;
    split1(a, h0, l0); split1(b, h1, l1);
    *(uint32_t*)ph = (uint32_t)h0 | ((uint32_t)h1 << 16);
    *(uint32_t*)pl = (uint32_t)l0 | ((uint32_t)l1 << 16);
}

__global__ void split_kernel(const float* __restrict__ in, __nv_bfloat16* __restrict__ oh,
                             __nv_bfloat16* __restrict__ ol, int n4) {
    int i = blockIdx.x * blockDim.x + threadIdx.x;
    if (i >= n4) return;
    float4 v = ((const float4*)in)[i];
    split_store4(oh + (size_t)i * 4, ol + (size_t)i * 4, v);
}

// ---------------- init ----------------
__global__ void zero_init_kernel(int n) {
    int i = blockIdx.x * blockDim.x + threadIdx.x;
    if (i < n) g_cnt[i] = 0;
    if (i < 128) { g_bnsum[i] = 0.f; g_bnsq[i] = 0.f; }
}

// ---------------- CSR build ----------------
__global__ void count_kernel(const int* __restrict__ edges, int E) {
    int e = blockIdx.x * blockDim.x + threadIdx.x;
    if (e >= E) return;
    atomicAdd(&g_cnt[edges[E + e]], 1);
}
__global__ void scan1_kernel(int n) {
    __shared__ int sh[1024];
    int tid = threadIdx.x;
    int i = blockIdx.x * 1024 + tid;
    int v = (i < n) ? g_cnt[i] : 0;
    sh[tid] = v;
    __syncthreads();
    for (int off = 1; off < 1024; off <<= 1) {
        int t = (tid >= off) ? sh[tid - off] : 0;
        __syncthreads();
        sh[tid] += t;
        __syncthreads();
    }
    if (i < n) g_rowstart[i] = sh[tid] - v;
    if (tid == 1023) g_bsum[blockIdx.x] = sh[1023];
}
__global__ void scan2_kernel(int nb) {
    if (threadIdx.x == 0) {
        int run = 0;
        for (int i = 0; i < nb; i++) { int t = g_bsum[i]; g_boff[i] = run; run += t; }
    }
}
__global__ void scan3_kernel(int n) {
    int i = blockIdx.x * blockDim.x + threadIdx.x;
    if (i < n) {
        int v = g_rowstart[i] + g_boff[i >> 10];
        g_rowstart[i] = v;
        g_cursor[i] = v;
    }
}
__global__ void fill_kernel(const int* __restrict__ edges, int E) {
    int e = blockIdx.x * blockDim.x + threadIdx.x;
    if (e >= E) return;
    int src = edges[e];
    int dst = edges[E + e];
    int pos = atomicAdd(&g_cursor[dst], 1);
    g_col[pos] = src;
}

// ---------------- HMMA (mma.sync bf16, 3-term split) GEMM ----------------
// C[M,Ntot] = act(A[M,K] @ B[Ntot,K]^T + bias [+ eps*resid]), fp32-equivalent
// precision via acc += Ah*Bh + Ah*Bl + Al*Bh.
// CTA tile 128x128, BK=64, SW128 swizzle, 2-stage cp.async pipeline.
// 256 threads = 8 warps in a 2x4 grid; warp tile 64x32 (m16n8k16 fragments).
#define STAGE_BYTES 65536            // 4 arrays * 128 rows * 128 B
#define GEMM_SMEM_BYTES (1024 + 2 * STAGE_BYTES)

__device__ __forceinline__ uint32_t sw128(uint32_t r, uint32_t u) {
    // byte offset of (row r, 16B-unit u) under SW128 swizzle
    return r * 128u + ((u ^ (r & 7u)) << 4);
}

__global__ __launch_bounds__(256, 1)
void hmma_gemm(const __nv_bfloat16* __restrict__ Ah, const __nv_bfloat16* __restrict__ Al,
               const __nv_bfloat16* __restrict__ Bh, const __nv_bfloat16* __restrict__ Bl,
               const float* __restrict__ bias,
               float* __restrict__ Cf,
               __nv_bfloat16* __restrict__ Ch, __nv_bfloat16* __restrict__ Cl,
               int M, int Ntot, int K, int relu,
               const float* __restrict__ resid, const float* __restrict__ eps_ptr)
{
    extern __shared__ char dsm[];
    uint32_t sb0 = smem_u32(dsm);
    uint32_t base0 = (sb0 + 1023u) & ~1023u;   // 1KB-aligned start

    int tid = threadIdx.x;
    int lane = tid & 31;
    int wid = tid >> 5;
    int wm = wid >> 2;        // 0..1 -> 64-row half
    int wn = wid & 3;         // 0..3 -> 32-col quarter
    int bm = blockIdx.y * 128, bn = blockIdx.x * 128;

    float acc[4][4][4];
#pragma unroll
    for (int i = 0; i < 4; i++)
#pragma unroll
        for (int j = 0; j < 4; j++)
#pragma unroll
            for (int k = 0; k < 4; k++) acc[i][j][k] = 0.f;

    const int NSt = K >> 6;

    const __nv_bfloat16* srcs[4] = { Ah, Al, Bh, Bl };
    const int rbase[4] = { bm, bm, bn, bn };
    const int rmax[4]  = { M - 1, M - 1, Ntot - 1, Ntot - 1 };

    // --- stage loader: 4 arrays x 128 rows x 8 16B-units, 16 cp.async per thread
    auto load_stage = [&](int s) {
        uint32_t buf = base0 + (uint32_t)(s & 1) * STAGE_BYTES;
        int kc = s * 64;
#pragma unroll
        for (int t = 0; t < 4; t++) {
            const __nv_bfloat16* src = srcs[t];
            int rb = rbase[t], rm = rmax[t];
            uint32_t dbase = buf + t * 16384u;
#pragma unroll
            for (int i = 0; i < 4; i++) {
                int idx = tid + i * 256;
                uint32_t r = (uint32_t)(idx >> 3);
                uint32_t u = (uint32_t)(idx & 7);
                int gr = rb + (int)r; if (gr > rm) gr = rm;
                cpasync16(dbase + sw128(r, u), src + (size_t)gr * K + kc + u * 8);
            }
        }
        cp_commit();
    };

    load_stage(0);
    for (int s = 0; s < NSt; s++) {
        if (s + 1 < NSt) { load_stage(s + 1); cp_wait1(); }
        else cp_wait0();
        __syncthreads();

        uint32_t buf = base0 + (uint32_t)(s & 1) * STAGE_BYTES;
#pragma unroll
        for (int ks = 0; ks < 4; ks++) {
            // B fragments: 2 x ldmatrix.x4, each covers two 8-wide n tiles
            uint32_t bh[4][2], bl[4][2];
#pragma unroll
            for (int jp = 0; jp < 2; jp++) {
                uint32_t n0 = (uint32_t)(wn * 32 + jp * 16);
                uint32_t r = n0 + (uint32_t)(lane & 7) + (uint32_t)((lane >> 4) << 3);
                uint32_t u = (uint32_t)(ks * 2 + ((lane >> 3) & 1));
                uint32_t off = sw128(r, u);
                uint32_t t4[4];
                ldsm4(t4, buf + 32768u + off);
                bh[jp * 2][0] = t4[0]; bh[jp * 2][1] = t4[1];
                bh[jp * 2 + 1][0] = t4[2]; bh[jp * 2 + 1][1] = t4[3];
                ldsm4(t4, buf + 49152u + off);
                bl[jp * 2][0] = t4[0]; bl[jp * 2][1] = t4[1];
                bl[jp * 2 + 1][0] = t4[2]; bl[jp * 2 + 1][1] = t4[3];
            }
#pragma unroll
            for (int mi = 0; mi < 4; mi++) {
                uint32_t m0 = (uint32_t)(wm * 64 + mi * 16);
                uint32_t r = m0 + (uint32_t)(lane & 15);
                uint32_t u = (uint32_t)(ks * 2 + (lane >> 4));
                uint32_t off = sw128(r, u);
                uint32_t ahf[4], alf[4];
                ldsm4(ahf, buf + off);
                ldsm4(alf, buf + 16384u + off);
#pragma unroll
                for (int ni = 0; ni < 4; ni++) {
                    mma_bf16(acc[mi][ni], ahf, bh[ni]);
                    mma_bf16(acc[mi][ni], ahf, bl[ni]);
                    mma_bf16(acc[mi][ni], alf, bh[ni]);
                }
            }
        }
        __syncthreads();
    }

    // ---------------- epilogue ----------------
    float e = resid ? __ldg(eps_ptr) : 0.f;
#pragma unroll
    for (int mi = 0; mi < 4; mi++) {
#pragma unroll
        for (int rr = 0; rr < 2; rr++) {
            int gr = bm + wm * 64 + mi * 16 + (lane >> 2) + rr * 8;
            if (gr >= M) continue;
#pragma unroll
            for (int ni = 0; ni < 4; ni++) {
                int gc = bn + wn * 32 + ni * 8 + (lane & 3) * 2;
                float v0 = acc[mi][ni][rr * 2 + 0];
                float v1 = acc[mi][ni][rr * 2 + 1];
                float2 bv = *(const float2*)(bias + gc);
                v0 += bv.x; v1 += bv.y;
                if (resid) {
                    float2 rv = *(const float2*)(resid + (size_t)gr * Ntot + gc);
                    v0 += e * rv.x; v1 += e * rv.y;
                }
                if (relu) { v0 = fmaxf(v0, 0.f); v1 = fmaxf(v1, 0.f); }
                if (Cf) {
                    *(float2*)(Cf + (size_t)gr * Ntot + gc) = make_float2(v0, v1);
                } else {
                    split_store2(Ch + (size_t)gr * Ntot + gc,
                                 Cl + (size_t)gr * Ntot + gc, v0, v1);
                }
            }
        }
    }
}

// ---------------- warp-per-node gather + segment sum/max ----------------
__global__ void gather_reduce_kernel(const float* __restrict__ x, int n) {
    int gt = blockIdx.x * blockDim.x + threadIdx.x;
    int node = gt >> 5;
    if (node >= n) return;
    int lane = gt & 31;
    int start = g_rowstart[node];
    int deg = g_cnt[node];
    float4 s = make_float4(0.f, 0.f, 0.f, 0.f);
    float4 m = make_float4(-1e30f, -1e30f, -1e30f, -1e30f);
    int j = 0;
    for (; j + 2 <= deg; j += 2) {
        int nb0 = g_col[start + j], nb1 = g_col[start + j + 1];
        float4 x0 = __ldg((const float4*)(x + (size_t)nb0 * 128 + lane * 4));
        float4 x1 = __ldg((const float4*)(x + (size_t)nb1 * 128 + lane * 4));
        float4 i0 = __ldg((const float4*)(g_xi + (size_t)nb0 * 128 + lane * 4));
        float4 i1 = __ldg((const float4*)(g_xi + (size_t)nb1 * 128 + lane * 4));
        s.x += x0.x + x1.x; s.y += x0.y + x1.y; s.z += x0.z + x1.z; s.w += x0.w + x1.w;
        m.x = fmaxf(m.x, fmaxf(i0.x, i1.x)); m.y = fmaxf(m.y, fmaxf(i0.y, i1.y));
        m.z = fmaxf(m.z, fmaxf(i0.z, i1.z)); m.w = fmaxf(m.w, fmaxf(i0.w, i1.w));
    }
    if (j < deg) {
        int nb = g_col[start + j];
        float4 xv = __ldg((const float4*)(x + (size_t)nb * 128 + lane * 4));
        float4 iv = __ldg((const float4*)(g_xi + (size_t)nb * 128 + lane * 4));
        s.x += xv.x; s.y += xv.y; s.z += xv.z; s.w += xv.w;
        m.x = fmaxf(m.x, iv.x); m.y = fmaxf(m.y, iv.y);
        m.z = fmaxf(m.z, iv.z); m.w = fmaxf(m.w, iv.w);
    }
    if (deg == 0) m = make_float4(0.f, 0.f, 0.f, 0.f);
    split_store4(g_cat_h + (size_t)node * 256 + lane * 4,
                 g_cat_l + (size_t)node * 256 + lane * 4, s);
    split_store4(g_am_h + (size_t)node * 128 + lane * 4,
                 g_am_l + (size_t)node * 128 + lane * 4, m);
}

// ---------------- GRU cell elementwise ----------------
__device__ __forceinline__ float gru1(float ir, float hr, float iz, float hz,
                                      float inn, float hn, float xv) {
    float r = 1.f / (1.f + expf(-(ir + hr)));
    float z = 1.f / (1.f + expf(-(iz + hz)));
    float nc = tanhf(inn + r * hn);
    return (1.f - z) * nc + z * xv;
}

__global__ void gru_kernel(const float* __restrict__ x, int M) {
    int idx = blockIdx.x * blockDim.x + threadIdx.x;
    if (idx >= M * 32) return;
    int node = idx >> 5;
    int c = (idx & 31) * 4;
    const float* gi = g_gi + (size_t)node * 384;
    const float* gh = g_gh + (size_t)node * 384;
    float4 ir = *(const float4*)(gi + c);
    float4 iz = *(const float4*)(gi + 128 + c);
    float4 in = *(const float4*)(gi + 256 + c);
    float4 hr = *(const float4*)(gh + c);
    float4 hz = *(const float4*)(gh + 128 + c);
    float4 hn = *(const float4*)(gh + 256 + c);
    float4 xv = *(const float4*)(x + (size_t)node * 128 + c);
    float4 o;
    o.x = gru1(ir.x, hr.x, iz.x, hz.x, in.x, hn.x, xv.x);
    o.y = gru1(ir.y, hr.y, iz.y, hz.y, in.y, hn.y, xv.y);
    o.z = gru1(ir.z, hr.z, iz.z, hz.z, in.z, hn.z, xv.z);
    o.w = gru1(ir.w, hr.w, iz.w, hz.w, in.w, hn.w, xv.w);
    split_store4(g_cat_h + (size_t)node * 256 + 128 + c,
                 g_cat_l + (size_t)node * 256 + 128 + c, o);
}

// ---------------- batchnorm ----------------
__global__ void bn_reduce_kernel(const float* __restrict__ h2, int M, int chunk) {
    int c = threadIdx.x;
    int r0 = blockIdx.x * chunk;
    int r1 = min(r0 + chunk, M);
    float s = 0.f, q = 0.f;
    for (int r = r0; r < r1; r++) {
        float v = h2[(size_t)r * 128 + c];
        s += v; q += v * v;
    }
    atomicAdd(&g_bnsum[c], s);
    atomicAdd(&g_bnsq[c], q);
}

__global__ void bn_norm_kernel(float* __restrict__ out, const float* __restrict__ gamma,
                               const float* __restrict__ beta, int M, float invM) {
    int idx = blockIdx.x * blockDim.x + threadIdx.x;
    if (idx >= M * 32) return;
    int node = idx >> 5;
    int c = (idx & 31) * 4;
    float4 v = *(float4*)(out + (size_t)node * 128 + c);
    float4 sm = *(const float4*)(g_bnsum + c);
    float4 sq = *(const float4*)(g_bnsq + c);
    float4 gm = *(const float4*)(gamma + c);
    float4 bt = *(const float4*)(beta + c);
    float4 o;
    { float mean = sm.x * invM, var = sq.x * invM - mean * mean;
      o.x = gm.x * (v.x - mean) * rsqrtf(var + 1e-5f) + bt.x; }
    { float mean = sm.y * invM, var = sq.y * invM - mean * mean;
      o.y = gm.y * (v.y - mean) * rsqrtf(var + 1e-5f) + bt.y; }
    { float mean = sm.z * invM, var = sq.z * invM - mean * mean;
      o.z = gm.z * (v.z - mean) * rsqrtf(var + 1e-5f) + bt.z; }
    { float mean = sm.w * invM, var = sq.w * invM - mean * mean;
      o.w = gm.w * (v.w - mean) * rsqrtf(var + 1e-5f) + bt.w; }
    *(float4*)(out + (size_t)node * 128 + c) = o;
}

// ---------------- launch ----------------
extern "C" void kernel_launch(void* const* d_in, const int* in_sizes, int n_in,
                              void* d_out, int out_size) {
    const float* x       = (const float*)d_in[0];
    const int*   edges   = (const int*)d_in[1];
    const float* W_aff   = (const float*)d_in[2];
    const float* b_aff   = (const float*)d_in[3];
    const float* W_ih    = (const float*)d_in[4];
    const float* b_ih    = (const float*)d_in[5];
    const float* W_hh    = (const float*)d_in[6];
    const float* b_hh    = (const float*)d_in[7];
    const float* W_merge = (const float*)d_in[8];
    const float* b_merge = (const float*)d_in[9];
    const float* eps     = (const float*)d_in[10];
    const float* W1      = (const float*)d_in[11];
    const float* b1      = (const float*)d_in[12];
    const float* W2      = (const float*)d_in[13];
    const float* b2      = (const float*)d_in[14];
    const float* gamma   = (const float*)d_in[15];
    const float* beta    = (const float*)d_in[16];
    float* out = (float*)d_out;

    int M = in_sizes[0] / 128;
    int E = in_sizes[1] / 2;

    float *p_xi, *p_gh, *p_gi;
    __nv_bfloat16 *p_xh, *p_xl, *p_amh, *p_aml, *p_ch, *p_cl, *p_hh, *p_hl, *p_th, *p_tl, *p_wh, *p_wl;
    cudaGetSymbolAddress((void**)&p_xi, g_xi);
    cudaGetSymbolAddress((void**)&p_gh, g_gh);
    cudaGetSymbolAddress((void**)&p_gi, g_gi);
    cudaGetSymbolAddress((void**)&p_xh, g_x_h);
    cudaGetSymbolAddress((void**)&p_xl, g_x_l);
    cudaGetSymbolAddress((void**)&p_amh, g_am_h);
    cudaGetSymbolAddress((void**)&p_aml, g_am_l);
    cudaGetSymbolAddress((void**)&p_ch, g_cat_h);
    cudaGetSymbolAddress((void**)&p_cl, g_cat_l);
    cudaGetSymbolAddress((void**)&p_hh, g_hh_h);
    cudaGetSymbolAddress((void**)&p_hl, g_hh_l);
    cudaGetSymbolAddress((void**)&p_th, g_t_h);
    cudaGetSymbolAddress((void**)&p_tl, g_t_l);
    cudaGetSymbolAddress((void**)&p_wh, g_w_h);
    cudaGetSymbolAddress((void**)&p_wl, g_w_l);

    cudaFuncSetAttribute(hmma_gemm, cudaFuncAttributeMaxDynamicSharedMemorySize, GEMM_SMEM_BYTES);

    // CSR build
    zero_init_kernel<<<(M + 255) / 256, 256>>>(M);
    count_kernel<<<(E + 255) / 256, 256>>>(edges, E);
    int nb = (M + 1023) / 1024;
    scan1_kernel<<<nb, 1024>>>(M);
    scan2_kernel<<<1, 32>>>(nb);
    scan3_kernel<<<(M + 255) / 256, 256>>>(M);
    fill_kernel<<<(E + 255) / 256, 256>>>(edges, E);

    // bf16 hi/lo splits: x and all weights
    {
        int n4 = M * 128 / 4;
        split_kernel<<<(n4 + 255) / 256, 256>>>(x, p_xh, p_xl, n4);
        split_kernel<<<(16384 / 4 + 255) / 256, 256>>>(W_aff, p_wh + OFF_AFF, p_wl + OFF_AFF, 16384 / 4);
        split_kernel<<<(49152 / 4 + 255) / 256, 256>>>(W_ih, p_wh + OFF_IH, p_wl + OFF_IH, 49152 / 4);
        split_kernel<<<(49152 / 4 + 255) / 256, 256>>>(W_hh, p_wh + OFF_HH, p_wl + OFF_HH, 49152 / 4);
        split_kernel<<<(32768 / 4 + 255) / 256, 256>>>(W_merge, p_wh + OFF_MG, p_wl + OFF_MG, 32768 / 4);
        split_kernel<<<(32768 / 4 + 255) / 256, 256>>>(W1, p_wh + OFF_W1, p_wl + OFF_W1, 32768 / 4);
        split_kernel<<<(32768 / 4 + 255) / 256, 256>>>(W2, p_wh + OFF_W2, p_wl + OFF_W2, 32768 / 4);
    }

    int mb = (M + 127) / 128;

    // xi = x @ W_aff^T + b_aff  (fp32 out, gather reads it)
    hmma_gemm<<<dim3(1, mb), 256, GEMM_SMEM_BYTES>>>(
        p_xh, p_xl, p_wh + OFF_AFF, p_wl + OFF_AFF, b_aff,
        p_xi, nullptr, nullptr, M, 128, 128, 0, nullptr, nullptr);
    // gh = x @ W_hh^T + b_hh  (fp32 out)
    hmma_gemm<<<dim3(3, mb), 256, GEMM_SMEM_BYTES>>>(
        p_xh, p_xl, p_wh + OFF_HH, p_wl + OFF_HH, b_hh,
        p_gh, nullptr, nullptr, M, 384, 128, 0, nullptr, nullptr);

    // segment sum(x) -> cat[:, :128], segment max(xi) -> am  (both bf16 pairs)
    gather_reduce_kernel<<<(M * 32 + 255) / 256, 256>>>(x, M);

    // gi = agg_max @ W_ih^T + b_ih  (fp32 out)
    hmma_gemm<<<dim3(3, mb), 256, GEMM_SMEM_BYTES>>>(
        p_amh, p_aml, p_wh + OFF_IH, p_wl + OFF_IH, b_ih,
        p_gi, nullptr, nullptr, M, 384, 128, 0, nullptr, nullptr);

    // GRU -> cat[:, 128:] (bf16 pair)
    gru_kernel<<<(M * 32 + 255) / 256, 256>>>(x, M);

    // h = cat @ W_merge^T + b_merge + eps*x  (bf16 pair out)
    hmma_gemm<<<dim3(1, mb), 256, GEMM_SMEM_BYTES>>>(
        p_ch, p_cl, p_wh + OFF_MG, p_wl + OFF_MG, b_merge,
        nullptr, p_hh, p_hl, M, 128, 256, 0, x, eps);

    // t = relu(h @ W1^T + b1)  (bf16 pair out)
    hmma_gemm<<<dim3(2, mb), 256, GEMM_SMEM_BYTES>>>(
        p_hh, p_hl, p_wh + OFF_W1, p_wl + OFF_W1, b1,
        nullptr, p_th, p_tl, M, 256, 128, 1, nullptr, nullptr);

    // out = relu(t @ W2^T + b2)  (fp32 out to d_out)
    hmma_gemm<<<dim3(1, mb), 256, GEMM_SMEM_BYTES>>>(
        p_th, p_tl, p_wh + OFF_W2, p_wl + OFF_W2, b2,
        out, nullptr, nullptr, M, 128, 256, 1, nullptr, nullptr);

    // batchnorm (train mode, biased variance)
    int chunk = (M + 1023) / 1024;
    bn_reduce_kernel<<<1024, 128>>>(out, M, chunk);
    bn_norm_kernel<<<(M * 32 + 255) / 256, 256>>>(out, gamma, beta, M, 1.0f / (float)M);
}

// round 5
// speedup vs baseline: 1.6904x; 1.0247x over previous
#include <cuda_runtime.h>
#include <cuda_bf16.h>
#include <math.h>
#include <stdint.h>

// ---------------- problem-size constants ----------------
#define NMAX 100000
#define EMAX 1600000

// ---------------- device scratch ----------------
__device__ float g_xi[(size_t)NMAX * 128];   // fp32: x @ W_aff^T + b_aff (gather reads it)
__device__ float g_gh[(size_t)NMAX * 384];   // fp32: x @ W_hh^T + b_hh  (GRU reads)
__device__ float g_gi[(size_t)NMAX * 384];   // fp32: agg_max @ W_ih^T + b_ih (GRU reads)

__device__ __align__(16) __nv_bfloat16 g_x_h[(size_t)NMAX * 128];
__device__ __align__(16) __nv_bfloat16 g_x_l[(size_t)NMAX * 128];
__device__ __align__(16) __nv_bfloat16 g_am_h[(size_t)NMAX * 128];
__device__ __align__(16) __nv_bfloat16 g_am_l[(size_t)NMAX * 128];
__device__ __align__(16) __nv_bfloat16 g_cat_h[(size_t)NMAX * 256];
__device__ __align__(16) __nv_bfloat16 g_cat_l[(size_t)NMAX * 256];
__device__ __align__(16) __nv_bfloat16 g_hh_h[(size_t)NMAX * 128];
__device__ __align__(16) __nv_bfloat16 g_hh_l[(size_t)NMAX * 128];
__device__ __align__(16) __nv_bfloat16 g_t_h[(size_t)NMAX * 256];
__device__ __align__(16) __nv_bfloat16 g_t_l[(size_t)NMAX * 256];
__device__ __align__(16) __nv_bfloat16 g_w_h[262144];
__device__ __align__(16) __nv_bfloat16 g_w_l[262144];

__device__ int g_cnt[NMAX];
__device__ int g_rowstart[NMAX];
__device__ int g_cursor[NMAX];
__device__ int g_col[EMAX];
__device__ int g_bsum[256];
__device__ int g_boff[256];
__device__ float g_bnsum[128];
__device__ float g_bnsq[128];

// weight offsets within g_w_h / g_w_l (elements)
#define OFF_AFF 0
#define OFF_IH  16384
#define OFF_HH  65536
#define OFF_MG  114688
#define OFF_W1  147456
#define OFF_W2  180224

// ---------------- low-level helpers (plain sm_80-class PTX) ----------------
__device__ __forceinline__ uint32_t smem_u32(const void* p) {
    uint32_t a;
    asm("{ .reg .u64 t; cvta.to.shared.u64 t, %1; cvt.u32.u64 %0, t; }" : "=r"(a) : "l"(p));
    return a;
}
__device__ __forceinline__ void cpasync16(uint32_t dst, const void* src) {
    asm volatile("cp.async.cg.shared.global [%0], [%1], 16;" :: "r"(dst), "l"(src));
}
__device__ __forceinline__ void cp_commit() {
    asm volatile("cp.async.commit_group;" ::: "memory");
}
__device__ __forceinline__ void cp_wait1() {
    asm volatile("cp.async.wait_group 1;" ::: "memory");
}
__device__ __forceinline__ void cp_wait0() {
    asm volatile("cp.async.wait_group 0;" ::: "memory");
}
__device__ __forceinline__ void ldsm4(uint32_t* r, uint32_t addr) {
    asm volatile("ldmatrix.sync.aligned.m8n8.x4.shared.b16 {%0,%1,%2,%3}, [%4];"
                 : "=r"(r[0]), "=r"(r[1]), "=r"(r[2]), "=r"(r[3]) : "r"(addr));
}
__device__ __forceinline__ void mma_bf16(float* d, const uint32_t* a, const uint32_t* b) {
    asm volatile(
        "mma.sync.aligned.m16n8k16.row.col.f32.bf16.bf16.f32 "
        "{%0,%1,%2,%3}, {%4,%5,%6,%7}, {%8,%9}, {%0,%1,%2,%3};"
        : "+f"(d[0]), "+f"(d[1]), "+f"(d[2]), "+f"(d[3])
        : "r"(a[0]), "r"(a[1]), "r"(a[2]), "r"(a[3]), "r"(b[0]), "r"(b[1]));
}

// ---------------- hi/lo bf16 split helpers ----------------
__device__ __forceinline__ void split1(float v, unsigned short& hb, unsigned short& lb) {
    __nv_bfloat16 h = __float2bfloat16(v);
    float hf = __bfloat162float(h);
    __nv_bfloat16 l = __float2bfloat16(v - hf);
    hb = __bfloat16_as_ushort(h);
    lb = __bfloat16_as_ushort(l);
}
__device__ __forceinline__ void split_store4(__nv_bfloat16* ph, __nv_bfloat16* pl, float4 v) {
    unsigned short h0, h1, h2, h3, l0, l1, l2, l3;
    split1(v.x, h0, l0); split1(v.y, h1, l1); split1(v.z, h2, l2); split1(v.w, h3, l3);
    uint2 uh = make_uint2((uint32_t)h0 | ((uint32_t)h1 << 16), (uint32_t)h2 | ((uint32_t)h3 << 16));
    uint2 ul = make_uint2((uint32_t)l0 | ((uint32_t)l1 << 16), (uint32_t)l2 | ((uint32_t)l3 << 16));
    *(uint2*)ph = uh;
    *(uint2*)pl = ul;
}
__device__ __forceinline__ void split_store2(__nv_bfloat16* ph, __nv_bfloat16* pl, float a, float b) {
    unsigned short h0, h1, l0, l1;
    split1(a, h0, l0); split1(b, h1, l1);
    *(uint32_t*)ph = (uint32_t)h0 | ((uint32_t)h1 << 16);
    *(uint32_t*)pl = (uint32_t)l0 | ((uint32_t)l1 << 16);
}

__global__ void split_kernel(const float* __restrict__ in, __nv_bfloat16* __restrict__ oh,
                             __nv_bfloat16* __restrict__ ol, int n4) {
    int i = blockIdx.x * blockDim.x + threadIdx.x;
    if (i >= n4) return;
    float4 v = ((const float4*)in)[i];
    split_store4(oh + (size_t)i * 4, ol + (size_t)i * 4, v);
}

// All six weights in one launch. float4-index ranges (cumulative):
//   aff [0,4096) ih [4096,16384) hh [16384,28672) mg [28672,36864)
//   w1 [36864,45056) w2 [45056,53248)
// dest float4 index == global i (offsets line up with OFF_* / 4).
__global__ void split_weights_kernel(const float* __restrict__ Waff, const float* __restrict__ Wih,
                                     const float* __restrict__ Whh, const float* __restrict__ Wmg,
                                     const float* __restrict__ W1, const float* __restrict__ W2,
                                     __nv_bfloat16* __restrict__ oh, __nv_bfloat16* __restrict__ ol) {
    int i = blockIdx.x * blockDim.x + threadIdx.x;
    if (i >= 53248) return;
    const float* src; int base;
    if (i < 4096)       { src = Waff; base = 0; }
    else if (i < 16384) { src = Wih;  base = 4096; }
    else if (i < 28672) { src = Whh;  base = 16384; }
    else if (i < 36864) { src = Wmg;  base = 28672; }
    else if (i < 45056) { src = W1;   base = 36864; }
    else                { src = W2;   base = 45056; }
    float4 v = ((const float4*)src)[i - base];
    split_store4(oh + (size_t)i * 4, ol + (size_t)i * 4, v);
}

// ---------------- init ----------------
__global__ void zero_init_kernel(int n) {
    int i = blockIdx.x * blockDim.x + threadIdx.x;
    if (i < n) g_cnt[i] = 0;
    if (i < 128) { g_bnsum[i] = 0.f; g_bnsq[i] = 0.f; }
}

// ---------------- CSR build ----------------
__global__ void count_kernel(const int* __restrict__ edges, int E) {
    int e = blockIdx.x * blockDim.x + threadIdx.x;
    if (e >= E) return;
    atomicAdd(&g_cnt[edges[E + e]], 1);
}
__global__ void scan1_kernel(int n) {
    __shared__ int sh[1024];
    int tid = threadIdx.x;
    int i = blockIdx.x * 1024 + tid;
    int v = (i < n) ? g_cnt[i] : 0;
    sh[tid] = v;
    __syncthreads();
    for (int off = 1; off < 1024; off <<= 1) {
        int t = (tid >= off) ? sh[tid - off] : 0;
        __syncthreads();
        sh[tid] += t;
        __syncthreads();
    }
    if (i < n) g_rowstart[i] = sh[tid] - v;
    if (tid == 1023) g_bsum[blockIdx.x] = sh[1023];
}
__global__ void scan2_kernel(int nb) {   // block-parallel scan, nb <= 128
    __shared__ int sh[128];
    int t = threadIdx.x;
    int v = (t < nb) ? g_bsum[t] : 0;
    sh[t] = v;
    __syncthreads();
    for (int off = 1; off < 128; off <<= 1) {
        int u = (t >= off) ? sh[t - off] : 0;
        __syncthreads();
        sh[t] += u;
        __syncthreads();
    }
    if (t < nb) g_boff[t] = sh[t] - v;   // exclusive
}
__global__ void scan3_kernel(int n) {
    int i = blockIdx.x * blockDim.x + threadIdx.x;
    if (i < n) {
        int v = g_rowstart[i] + g_boff[i >> 10];
        g_rowstart[i] = v;
        g_cursor[i] = v;
    }
}
__global__ void fill_kernel(const int* __restrict__ edges, int E) {
    int e = blockIdx.x * blockDim.x + threadIdx.x;
    if (e >= E) return;
    int src = edges[e];
    int dst = edges[E + e];
    int pos = atomicAdd(&g_cursor[dst], 1);
    g_col[pos] = src;
}

// ---------------- HMMA (mma.sync bf16, 3-term split) GEMM ----------------
#define STAGE_BYTES 65536            // 4 arrays * 128 rows * 128 B
#define GEMM_SMEM_BYTES (1024 + 2 * STAGE_BYTES)

__device__ __forceinline__ uint32_t sw128(uint32_t r, uint32_t u) {
    return r * 128u + ((u ^ (r & 7u)) << 4);
}

__global__ __launch_bounds__(256, 1)
void hmma_gemm(const __nv_bfloat16* __restrict__ Ah, const __nv_bfloat16* __restrict__ Al,
               const __nv_bfloat16* __restrict__ Bh, const __nv_bfloat16* __restrict__ Bl,
               const float* __restrict__ bias,
               float* __restrict__ Cf,
               __nv_bfloat16* __restrict__ Ch, __nv_bfloat16* __restrict__ Cl,
               int M, int Ntot, int K, int relu,
               const float* __restrict__ resid, const float* __restrict__ eps_ptr)
{
    extern __shared__ char dsm[];
    uint32_t sb0 = smem_u32(dsm);
    uint32_t base0 = (sb0 + 1023u) & ~1023u;

    int tid = threadIdx.x;
    int lane = tid & 31;
    int wid = tid >> 5;
    int wm = wid >> 2;
    int wn = wid & 3;
    int bm = blockIdx.y * 128, bn = blockIdx.x * 128;

    float acc[4][4][4];
#pragma unroll
    for (int i = 0; i < 4; i++)
#pragma unroll
        for (int j = 0; j < 4; j++)
#pragma unroll
            for (int k = 0; k < 4; k++) acc[i][j][k] = 0.f;

    const int NSt = K >> 6;

    const __nv_bfloat16* srcs[4] = { Ah, Al, Bh, Bl };
    const int rbase[4] = { bm, bm, bn, bn };
    const int rmax[4]  = { M - 1, M - 1, Ntot - 1, Ntot - 1 };

    auto load_stage = [&](int s) {
        uint32_t buf = base0 + (uint32_t)(s & 1) * STAGE_BYTES;
        int kc = s * 64;
#pragma unroll
        for (int t = 0; t < 4; t++) {
            const __nv_bfloat16* src = srcs[t];
            int rb = rbase[t], rm = rmax[t];
            uint32_t dbase = buf + t * 16384u;
#pragma unroll
            for (int i = 0; i < 4; i++) {
                int idx = tid + i * 256;
                uint32_t r = (uint32_t)(idx >> 3);
                uint32_t u = (uint32_t)(idx & 7);
                int gr = rb + (int)r; if (gr > rm) gr = rm;
                cpasync16(dbase + sw128(r, u), src + (size_t)gr * K + kc + u * 8);
            }
        }
        cp_commit();
    };

    load_stage(0);
    for (int s = 0; s < NSt; s++) {
        if (s + 1 < NSt) { load_stage(s + 1); cp_wait1(); }
        else cp_wait0();
        __syncthreads();

        uint32_t buf = base0 + (uint32_t)(s & 1) * STAGE_BYTES;
#pragma unroll
        for (int ks = 0; ks < 4; ks++) {
            uint32_t bh[4][2], bl[4][2];
#pragma unroll
            for (int jp = 0; jp < 2; jp++) {
                uint32_t n0 = (uint32_t)(wn * 32 + jp * 16);
                uint32_t r = n0 + (uint32_t)(lane & 7) + (uint32_t)((lane >> 4) << 3);
                uint32_t u = (uint32_t)(ks * 2 + ((lane >> 3) & 1));
                uint32_t off = sw128(r, u);
                uint32_t t4[4];
                ldsm4(t4, buf + 32768u + off);
                bh[jp * 2][0] = t4[0]; bh[jp * 2][1] = t4[1];
                bh[jp * 2 + 1][0] = t4[2]; bh[jp * 2 + 1][1] = t4[3];
                ldsm4(t4, buf + 49152u + off);
                bl[jp * 2][0] = t4[0]; bl[jp * 2][1] = t4[1];
                bl[jp * 2 + 1][0] = t4[2]; bl[jp * 2 + 1][1] = t4[3];
            }
#pragma unroll
            for (int mi = 0; mi < 4; mi++) {
                uint32_t m0 = (uint32_t)(wm * 64 + mi * 16);
                uint32_t r = m0 + (uint32_t)(lane & 15);
                uint32_t u = (uint32_t)(ks * 2 + (lane >> 4));
                uint32_t off = sw128(r, u);
                uint32_t ahf[4], alf[4];
                ldsm4(ahf, buf + off);
                ldsm4(alf, buf + 16384u + off);
#pragma unroll
                for (int ni = 0; ni < 4; ni++) {
                    mma_bf16(acc[mi][ni], ahf, bh[ni]);
                    mma_bf16(acc[mi][ni], ahf, bl[ni]);
                    mma_bf16(acc[mi][ni], alf, bh[ni]);
                }
            }
        }
        __syncthreads();
    }

    // ---------------- epilogue ----------------
    float e = resid ? __ldg(eps_ptr) : 0.f;
#pragma unroll
    for (int mi = 0; mi < 4; mi++) {
#pragma unroll
        for (int rr = 0; rr < 2; rr++) {
            int gr = bm + wm * 64 + mi * 16 + (lane >> 2) + rr * 8;
            if (gr >= M) continue;
#pragma unroll
            for (int ni = 0; ni < 4; ni++) {
                int gc = bn + wn * 32 + ni * 8 + (lane & 3) * 2;
                float v0 = acc[mi][ni][rr * 2 + 0];
                float v1 = acc[mi][ni][rr * 2 + 1];
                float2 bv = *(const float2*)(bias + gc);
                v0 += bv.x; v1 += bv.y;
                if (resid) {
                    float2 rv = *(const float2*)(resid + (size_t)gr * Ntot + gc);
                    v0 += e * rv.x; v1 += e * rv.y;
                }
                if (relu) { v0 = fmaxf(v0, 0.f); v1 = fmaxf(v1, 0.f); }
                if (Cf) {
                    *(float2*)(Cf + (size_t)gr * Ntot + gc) = make_float2(v0, v1);
                } else {
                    split_store2(Ch + (size_t)gr * Ntot + gc,
                                 Cl + (size_t)gr * Ntot + gc, v0, v1);
                }
            }
        }
    }
}

// ---------------- warp-per-node gather + segment sum/max (unroll 4) ----------------
__global__ void gather_reduce_kernel(const float* __restrict__ x, int n) {
    int gt = blockIdx.x * blockDim.x + threadIdx.x;
    int node = gt >> 5;
    if (node >= n) return;
    int lane = gt & 31;
    int start = g_rowstart[node];
    int deg = g_cnt[node];
    float4 s = make_float4(0.f, 0.f, 0.f, 0.f);
    float4 m = make_float4(-1e30f, -1e30f, -1e30f, -1e30f);
    int j = 0;
    for (; j + 4 <= deg; j += 4) {
        int nb0 = g_col[start + j],     nb1 = g_col[start + j + 1];
        int nb2 = g_col[start + j + 2], nb3 = g_col[start + j + 3];
        float4 x0 = __ldg((const float4*)(x + (size_t)nb0 * 128 + lane * 4));
        float4 x1 = __ldg((const float4*)(x + (size_t)nb1 * 128 + lane * 4));
        float4 x2 = __ldg((const float4*)(x + (size_t)nb2 * 128 + lane * 4));
        float4 x3 = __ldg((const float4*)(x + (size_t)nb3 * 128 + lane * 4));
        float4 i0 = __ldg((const float4*)(g_xi + (size_t)nb0 * 128 + lane * 4));
        float4 i1 = __ldg((const float4*)(g_xi + (size_t)nb1 * 128 + lane * 4));
        float4 i2 = __ldg((const float4*)(g_xi + (size_t)nb2 * 128 + lane * 4));
        float4 i3 = __ldg((const float4*)(g_xi + (size_t)nb3 * 128 + lane * 4));
        s.x += (x0.x + x1.x) + (x2.x + x3.x);
        s.y += (x0.y + x1.y) + (x2.y + x3.y);
        s.z += (x0.z + x1.z) + (x2.z + x3.z);
        s.w += (x0.w + x1.w) + (x2.w + x3.w);
        m.x = fmaxf(m.x, fmaxf(fmaxf(i0.x, i1.x), fmaxf(i2.x, i3.x)));
        m.y = fmaxf(m.y, fmaxf(fmaxf(i0.y, i1.y), fmaxf(i2.y, i3.y)));
        m.z = fmaxf(m.z, fmaxf(fmaxf(i0.z, i1.z), fmaxf(i2.z, i3.z)));
        m.w = fmaxf(m.w, fmaxf(fmaxf(i0.w, i1.w), fmaxf(i2.w, i3.w)));
    }
    for (; j < deg; j++) {
        int nb = g_col[start + j];
        float4 xv = __ldg((const float4*)(x + (size_t)nb * 128 + lane * 4));
        float4 iv = __ldg((const float4*)(g_xi + (size_t)nb * 128 + lane * 4));
        s.x += xv.x; s.y += xv.y; s.z += xv.z; s.w += xv.w;
        m.x = fmaxf(m.x, iv.x); m.y = fmaxf(m.y, iv.y);
        m.z = fmaxf(m.z, iv.z); m.w = fmaxf(m.w, iv.w);
    }
    if (deg == 0) m = make_float4(0.f, 0.f, 0.f, 0.f);
    split_store4(g_cat_h + (size_t)node * 256 + lane * 4,
                 g_cat_l + (size_t)node * 256 + lane * 4, s);
    split_store4(g_am_h + (size_t)node * 128 + lane * 4,
                 g_am_l + (size_t)node * 128 + lane * 4, m);
}

// ---------------- GRU cell elementwise ----------------
__device__ __forceinline__ float gru1(float ir, float hr, float iz, float hz,
                                      float inn, float hn, float xv) {
    float r = 1.f / (1.f + expf(-(ir + hr)));
    float z = 1.f / (1.f + expf(-(iz + hz)));
    float nc = tanhf(inn + r * hn);
    return (1.f - z) * nc + z * xv;
}

__global__ void gru_kernel(const float* __restrict__ x, int M) {
    int idx = blockIdx.x * blockDim.x + threadIdx.x;
    if (idx >= M * 32) return;
    int node = idx >> 5;
    int c = (idx & 31) * 4;
    const float* gi = g_gi + (size_t)node * 384;
    const float* gh = g_gh + (size_t)node * 384;
    float4 ir = *(const float4*)(gi + c);
    float4 iz = *(const float4*)(gi + 128 + c);
    float4 in = *(const float4*)(gi + 256 + c);
    float4 hr = *(const float4*)(gh + c);
    float4 hz = *(const float4*)(gh + 128 + c);
    float4 hn = *(const float4*)(gh + 256 + c);
    float4 xv = *(const float4*)(x + (size_t)node * 128 + c);
    float4 o;
    o.x = gru1(ir.x, hr.x, iz.x, hz.x, in.x, hn.x, xv.x);
    o.y = gru1(ir.y, hr.y, iz.y, hz.y, in.y, hn.y, xv.y);
    o.z = gru1(ir.z, hr.z, iz.z, hz.z, in.z, hn.z, xv.z);
    o.w = gru1(ir.w, hr.w, iz.w, hz.w, in.w, hn.w, xv.w);
    split_store4(g_cat_h + (size_t)node * 256 + 128 + c,
                 g_cat_l + (size_t)node * 256 + 128 + c, o);
}

// ---------------- batchnorm ----------------
__global__ void bn_reduce_kernel(const float* __restrict__ h2, int M, int chunk) {
    int c = threadIdx.x;
    int r0 = blockIdx.x * chunk;
    int r1 = min(r0 + chunk, M);
    float s = 0.f, q = 0.f;
    for (int r = r0; r < r1; r++) {
        float v = h2[(size_t)r * 128 + c];
        s += v; q += v * v;
    }
    atomicAdd(&g_bnsum[c], s);
    atomicAdd(&g_bnsq[c], q);
}

__global__ void bn_norm_kernel(float* __restrict__ out, const float* __restrict__ gamma,
                               const float* __restrict__ beta, int M, float invM) {
    int idx = blockIdx.x * blockDim.x + threadIdx.x;
    if (idx >= M * 32) return;
    int node = idx >> 5;
    int c = (idx & 31) * 4;
    float4 v = *(float4*)(out + (size_t)node * 128 + c);
    float4 sm = *(const float4*)(g_bnsum + c);
    float4 sq = *(const float4*)(g_bnsq + c);
    float4 gm = *(const float4*)(gamma + c);
    float4 bt = *(const float4*)(beta + c);
    float4 o;
    { float mean = sm.x * invM, var = sq.x * invM - mean * mean;
      o.x = gm.x * (v.x - mean) * rsqrtf(var + 1e-5f) + bt.x; }
    { float mean = sm.y * invM, var = sq.y * invM - mean * mean;
      o.y = gm.y * (v.y - mean) * rsqrtf(var + 1e-5f) + bt.y; }
    { float mean = sm.z * invM, var = sq.z * invM - mean * mean;
      o.z = gm.z * (v.z - mean) * rsqrtf(var + 1e-5f) + bt.z; }
    { float mean = sm.w * invM, var = sq.w * invM - mean * mean;
      o.w = gm.w * (v.w - mean) * rsqrtf(var + 1e-5f) + bt.w; }
    *(float4*)(out + (size_t)node * 128 + c) = o;
}

// ---------------- launch ----------------
extern "C" void kernel_launch(void* const* d_in, const int* in_sizes, int n_in,
                              void* d_out, int out_size) {
    const float* x       = (const float*)d_in[0];
    const int*   edges   = (const int*)d_in[1];
    const float* W_aff   = (const float*)d_in[2];
    const float* b_aff   = (const float*)d_in[3];
    const float* W_ih    = (const float*)d_in[4];
    const float* b_ih    = (const float*)d_in[5];
    const float* W_hh    = (const float*)d_in[6];
    const float* b_hh    = (const float*)d_in[7];
    const float* W_merge = (const float*)d_in[8];
    const float* b_merge = (const float*)d_in[9];
    const float* eps     = (const float*)d_in[10];
    const float* W1      = (const float*)d_in[11];
    const float* b1      = (const float*)d_in[12];
    const float* W2      = (const float*)d_in[13];
    const float* b2      = (const float*)d_in[14];
    const float* gamma   = (const float*)d_in[15];
    const float* beta    = (const float*)d_in[16];
    float* out = (float*)d_out;

    int M = in_sizes[0] / 128;
    int E = in_sizes[1] / 2;

    float *p_xi, *p_gh, *p_gi;
    __nv_bfloat16 *p_xh, *p_xl, *p_amh, *p_aml, *p_ch, *p_cl, *p_hh, *p_hl, *p_th, *p_tl, *p_wh, *p_wl;
    cudaGetSymbolAddress((void**)&p_xi, g_xi);
    cudaGetSymbolAddress((void**)&p_gh, g_gh);
    cudaGetSymbolAddress((void**)&p_gi, g_gi);
    cudaGetSymbolAddress((void**)&p_xh, g_x_h);
    cudaGetSymbolAddress((void**)&p_xl, g_x_l);
    cudaGetSymbolAddress((void**)&p_amh, g_am_h);
    cudaGetSymbolAddress((void**)&p_aml, g_am_l);
    cudaGetSymbolAddress((void**)&p_ch, g_cat_h);
    cudaGetSymbolAddress((void**)&p_cl, g_cat_l);
    cudaGetSymbolAddress((void**)&p_hh, g_hh_h);
    cudaGetSymbolAddress((void**)&p_hl, g_hh_l);
    cudaGetSymbolAddress((void**)&p_th, g_t_h);
    cudaGetSymbolAddress((void**)&p_tl, g_t_l);
    cudaGetSymbolAddress((void**)&p_wh, g_w_h);
    cudaGetSymbolAddress((void**)&p_wl, g_w_l);

    cudaFuncSetAttribute(hmma_gemm, cudaFuncAttributeMaxDynamicSharedMemorySize, GEMM_SMEM_BYTES);

    // one-time stream/event resources (host objects, not device memory)
    static cudaStream_t s1 = nullptr;
    static cudaEvent_t evR = nullptr, evCSR = nullptr, evXI = nullptr, evGH = nullptr;
    if (!s1) {
        cudaStreamCreateWithFlags(&s1, cudaStreamNonBlocking);
        cudaEventCreateWithFlags(&evR, cudaEventDisableTiming);
        cudaEventCreateWithFlags(&evCSR, cudaEventDisableTiming);
        cudaEventCreateWithFlags(&evXI, cudaEventDisableTiming);
        cudaEventCreateWithFlags(&evGH, cudaEventDisableTiming);
    }
    cudaStream_t s0 = 0;  // capture-origin (legacy default) stream

    int mb = (M + 127) / 128;
    int nb = (M + 1023) / 1024;

    // root: zero counters (needed by CSR count and BN)
    zero_init_kernel<<<(M + 255) / 256, 256, 0, s0>>>(M);
    cudaEventRecord(evR, s0);

    // ---- branch s1: CSR build (depends only on edges + zeroed cnt) ----
    cudaStreamWaitEvent(s1, evR, 0);
    count_kernel<<<(E + 255) / 256, 256, 0, s1>>>(edges, E);
    scan1_kernel<<<nb, 1024, 0, s1>>>(M);
    scan2_kernel<<<1, 128, 0, s1>>>(nb);
    scan3_kernel<<<(M + 255) / 256, 256, 0, s1>>>(M);
    fill_kernel<<<(E + 255) / 256, 256, 0, s1>>>(edges, E);
    cudaEventRecord(evCSR, s1);

    // ---- main stream: splits + xi GEMM ----
    {
        int n4 = M * 128 / 4;
        split_kernel<<<(n4 + 255) / 256, 256, 0, s0>>>(x, p_xh, p_xl, n4);
        split_weights_kernel<<<(53248 + 255) / 256, 256, 0, s0>>>(
            W_aff, W_ih, W_hh, W_merge, W1, W2, p_wh, p_wl);
    }
    // xi = x @ W_aff^T + b_aff (fp32, read by gather)
    hmma_gemm<<<dim3(1, mb), 256, GEMM_SMEM_BYTES, s0>>>(
        p_xh, p_xl, p_wh + OFF_AFF, p_wl + OFF_AFF, b_aff,
        p_xi, nullptr, nullptr, M, 128, 128, 0, nullptr, nullptr);
    cudaEventRecord(evXI, s0);

    // ---- branch s1 (after xi + splits): gh GEMM, concurrent with gather ----
    cudaStreamWaitEvent(s1, evXI, 0);
    hmma_gemm<<<dim3(3, mb), 256, GEMM_SMEM_BYTES, s1>>>(
        p_xh, p_xl, p_wh + OFF_HH, p_wl + OFF_HH, b_hh,
        p_gh, nullptr, nullptr, M, 384, 128, 0, nullptr, nullptr);
    cudaEventRecord(evGH, s1);

    // ---- main stream: gather (needs CSR + xi) ----
    cudaStreamWaitEvent(s0, evCSR, 0);
    gather_reduce_kernel<<<(M * 32 + 255) / 256, 256, 0, s0>>>(x, M);

    // gi = agg_max @ W_ih^T + b_ih (fp32)
    hmma_gemm<<<dim3(3, mb), 256, GEMM_SMEM_BYTES, s0>>>(
        p_amh, p_aml, p_wh + OFF_IH, p_wl + OFF_IH, b_ih,
        p_gi, nullptr, nullptr, M, 384, 128, 0, nullptr, nullptr);

    // GRU (needs gi + gh) -> cat[:, 128:]
    cudaStreamWaitEvent(s0, evGH, 0);
    gru_kernel<<<(M * 32 + 255) / 256, 256, 0, s0>>>(x, M);

    // h = cat @ W_merge^T + b_merge + eps*x (bf16 pair)
    hmma_gemm<<<dim3(1, mb), 256, GEMM_SMEM_BYTES, s0>>>(
        p_ch, p_cl, p_wh + OFF_MG, p_wl + OFF_MG, b_merge,
        nullptr, p_hh, p_hl, M, 128, 256, 0, x, eps);

    // t = relu(h @ W1^T + b1) (bf16 pair)
    hmma_gemm<<<dim3(2, mb), 256, GEMM_SMEM_BYTES, s0>>>(
        p_hh, p_hl, p_wh + OFF_W1, p_wl + OFF_W1, b1,
        nullptr, p_th, p_tl, M, 256, 128, 1, nullptr, nullptr);

    // out = relu(t @ W2^T + b2) (fp32 -> d_out)
    hmma_gemm<<<dim3(1, mb), 256, GEMM_SMEM_BYTES, s0>>>(
        p_th, p_tl, p_wh + OFF_W2, p_wl + OFF_W2, b2,
        out, nullptr, nullptr, M, 128, 256, 1, nullptr, nullptr);

    // batchnorm (train mode, biased variance)
    int chunk = (M + 1023) / 1024;
    bn_reduce_kernel<<<1024, 128, 0, s0>>>(out, M, chunk);
    bn_norm_kernel<<<(M * 32 + 255) / 256, 256, 0, s0>>>(out, gamma, beta, M, 1.0f / (float)M);
}

// round 6
// speedup vs baseline: 1.7323x; 1.0247x over previous
#include <cuda_runtime.h>
#include <cuda_bf16.h>
#include <cuda_fp16.h>
#include <math.h>
#include <stdint.h>

// ---------------- problem-size constants ----------------
#define NMAX 100000
#define EMAX 1600000

// ---------------- device scratch ----------------
__device__ float g_gh[(size_t)NMAX * 384];   // fp32: x @ W_hh^T + b_hh  (GRU reads)
__device__ float g_gi[(size_t)NMAX * 384];   // fp32: agg_max @ W_ih^T + b_ih (GRU reads)

__device__ __align__(16) __half g_x_f16[(size_t)NMAX * 128];   // fp16 x (gather)
__device__ __align__(16) __half g_xi_f16[(size_t)NMAX * 128];  // fp16 xi (gather)

__device__ __align__(16) __nv_bfloat16 g_x_h[(size_t)NMAX * 128];
__device__ __align__(16) __nv_bfloat16 g_x_l[(size_t)NMAX * 128];
__device__ __align__(16) __nv_bfloat16 g_am_h[(size_t)NMAX * 128];
__device__ __align__(16) __nv_bfloat16 g_am_l[(size_t)NMAX * 128];
__device__ __align__(16) __nv_bfloat16 g_cat_h[(size_t)NMAX * 256];
__device__ __align__(16) __nv_bfloat16 g_cat_l[(size_t)NMAX * 256];
__device__ __align__(16) __nv_bfloat16 g_hh_h[(size_t)NMAX * 128];
__device__ __align__(16) __nv_bfloat16 g_hh_l[(size_t)NMAX * 128];
__device__ __align__(16) __nv_bfloat16 g_t_h[(size_t)NMAX * 256];
__device__ __align__(16) __nv_bfloat16 g_t_l[(size_t)NMAX * 256];
__device__ __align__(16) __nv_bfloat16 g_w_h[262144];
__device__ __align__(16) __nv_bfloat16 g_w_l[262144];

__device__ int g_cnt[NMAX];
__device__ int g_rowstart[NMAX];
__device__ int g_cursor[NMAX];
__device__ int g_col[EMAX];
__device__ int g_bsum[256];
__device__ int g_boff[256];
__device__ float g_bnsum[128];
__device__ float g_bnsq[128];

// weight offsets within g_w_h / g_w_l (elements)
#define OFF_AFF 0
#define OFF_IH  16384
#define OFF_HH  65536
#define OFF_MG  114688
#define OFF_W1  147456
#define OFF_W2  180224

// ---------------- low-level helpers (plain sm_80-class PTX) ----------------
__device__ __forceinline__ uint32_t smem_u32(const void* p) {
    uint32_t a;
    asm("{ .reg .u64 t; cvta.to.shared.u64 t, %1; cvt.u32.u64 %0, t; }" : "=r"(a) : "l"(p));
    return a;
}
__device__ __forceinline__ void cpasync16(uint32_t dst, const void* src) {
    asm volatile("cp.async.cg.shared.global [%0], [%1], 16;" :: "r"(dst), "l"(src));
}
__device__ __forceinline__ void cp_commit() {
    asm volatile("cp.async.commit_group;" ::: "memory");
}
__device__ __forceinline__ void cp_wait1() {
    asm volatile("cp.async.wait_group 1;" ::: "memory");
}
__device__ __forceinline__ void cp_wait0() {
    asm volatile("cp.async.wait_group 0;" ::: "memory");
}
__device__ __forceinline__ void ldsm4(uint32_t* r, uint32_t addr) {
    asm volatile("ldmatrix.sync.aligned.m8n8.x4.shared.b16 {%0,%1,%2,%3}, [%4];"
                 : "=r"(r[0]), "=r"(r[1]), "=r"(r[2]), "=r"(r[3]) : "r"(addr));
}
__device__ __forceinline__ void mma_bf16(float* d, const uint32_t* a, const uint32_t* b) {
    asm volatile(
        "mma.sync.aligned.m16n8k16.row.col.f32.bf16.bf16.f32 "
        "{%0,%1,%2,%3}, {%4,%5,%6,%7}, {%8,%9}, {%0,%1,%2,%3};"
        : "+f"(d[0]), "+f"(d[1]), "+f"(d[2]), "+f"(d[3])
        : "r"(a[0]), "r"(a[1]), "r"(a[2]), "r"(a[3]), "r"(b[0]), "r"(b[1]));
}

// ---------------- hi/lo bf16 split helpers ----------------
__device__ __forceinline__ void split1(float v, unsigned short& hb, unsigned short& lb) {
    __nv_bfloat16 h = __float2bfloat16(v);
    float hf = __bfloat162float(h);
    __nv_bfloat16 l = __float2bfloat16(v - hf);
    hb = __bfloat16_as_ushort(h);
    lb = __bfloat16_as_ushort(l);
}
__device__ __forceinline__ void split_store4(__nv_bfloat16* ph, __nv_bfloat16* pl, float4 v) {
    unsigned short h0, h1, h2, h3, l0, l1, l2, l3;
    split1(v.x, h0, l0); split1(v.y, h1, l1); split1(v.z, h2, l2); split1(v.w, h3, l3);
    uint2 uh = make_uint2((uint32_t)h0 | ((uint32_t)h1 << 16), (uint32_t)h2 | ((uint32_t)h3 << 16));
    uint2 ul = make_uint2((uint32_t)l0 | ((uint32_t)l1 << 16), (uint32_t)l2 | ((uint32_t)l3 << 16));
    *(uint2*)ph = uh;
    *(uint2*)pl = ul;
}
__device__ __forceinline__ void split_store2(__nv_bfloat16* ph, __nv_bfloat16* pl, float a, float b) {
    unsigned short h0, h1, l0, l1;
    split1(a, h0, l0); split1(b, h1, l1);
    *(uint32_t*)ph = (uint32_t)h0 | ((uint32_t)h1 << 16);
    *(uint32_t*)pl = (uint32_t)l0 | ((uint32_t)l1 << 16);
}

// x: bf16 hi/lo pair + fp16 copy (for gather)
__global__ void split_kernel(const float* __restrict__ in, __nv_bfloat16* __restrict__ oh,
                             __nv_bfloat16* __restrict__ ol, __half* __restrict__ of, int n4) {
    int i = blockIdx.x * blockDim.x + threadIdx.x;
    if (i >= n4) return;
    float4 v = ((const float4*)in)[i];
    split_store4(oh + (size_t)i * 4, ol + (size_t)i * 4, v);
    __half2 f0 = __floats2half2_rn(v.x, v.y);
    __half2 f1 = __floats2half2_rn(v.z, v.w);
    *(uint2*)(of + (size_t)i * 4) = make_uint2(*(uint32_t*)&f0, *(uint32_t*)&f1);
}

// All six weights in one launch. float4-index ranges (cumulative):
//   aff [0,4096) ih [4096,16384) hh [16384,28672) mg [28672,36864)
//   w1 [36864,45056) w2 [45056,53248)
__global__ void split_weights_kernel(const float* __restrict__ Waff, const float* __restrict__ Wih,
                                     const float* __restrict__ Whh, const float* __restrict__ Wmg,
                                     const float* __restrict__ W1, const float* __restrict__ W2,
                                     __nv_bfloat16* __restrict__ oh, __nv_bfloat16* __restrict__ ol) {
    int i = blockIdx.x * blockDim.x + threadIdx.x;
    if (i >= 53248) return;
    const float* src; int base;
    if (i < 4096)       { src = Waff; base = 0; }
    else if (i < 16384) { src = Wih;  base = 4096; }
    else if (i < 28672) { src = Whh;  base = 16384; }
    else if (i < 36864) { src = Wmg;  base = 28672; }
    else if (i < 45056) { src = W1;   base = 36864; }
    else                { src = W2;   base = 45056; }
    float4 v = ((const float4*)src)[i - base];
    split_store4(oh + (size_t)i * 4, ol + (size_t)i * 4, v);
}

// ---------------- init ----------------
__global__ void zero_init_kernel(int n) {
    int i = blockIdx.x * blockDim.x + threadIdx.x;
    if (i < n) g_cnt[i] = 0;
    if (i < 128) { g_bnsum[i] = 0.f; g_bnsq[i] = 0.f; }
}

// ---------------- CSR build ----------------
__global__ void count_kernel(const int* __restrict__ edges, int E) {
    int e = blockIdx.x * blockDim.x + threadIdx.x;
    if (e >= E) return;
    atomicAdd(&g_cnt[edges[E + e]], 1);
}
__global__ void scan1_kernel(int n) {
    __shared__ int sh[1024];
    int tid = threadIdx.x;
    int i = blockIdx.x * 1024 + tid;
    int v = (i < n) ? g_cnt[i] : 0;
    sh[tid] = v;
    __syncthreads();
    for (int off = 1; off < 1024; off <<= 1) {
        int t = (tid >= off) ? sh[tid - off] : 0;
        __syncthreads();
        sh[tid] += t;
        __syncthreads();
    }
    if (i < n) g_rowstart[i] = sh[tid] - v;
    if (tid == 1023) g_bsum[blockIdx.x] = sh[1023];
}
__global__ void scan2_kernel(int nb) {   // block-parallel scan, nb <= 128
    __shared__ int sh[128];
    int t = threadIdx.x;
    int v = (t < nb) ? g_bsum[t] : 0;
    sh[t] = v;
    __syncthreads();
    for (int off = 1; off < 128; off <<= 1) {
        int u = (t >= off) ? sh[t - off] : 0;
        __syncthreads();
        sh[t] += u;
        __syncthreads();
    }
    if (t < nb) g_boff[t] = sh[t] - v;   // exclusive
}
__global__ void scan3_kernel(int n) {
    int i = blockIdx.x * blockDim.x + threadIdx.x;
    if (i < n) {
        int v = g_rowstart[i] + g_boff[i >> 10];
        g_rowstart[i] = v;
        g_cursor[i] = v;
    }
}
__global__ void fill_kernel(const int* __restrict__ edges, int E) {
    int e = blockIdx.x * blockDim.x + threadIdx.x;
    if (e >= E) return;
    int src = edges[e];
    int dst = edges[E + e];
    int pos = atomicAdd(&g_cursor[dst], 1);
    g_col[pos] = src;
}

// ---------------- HMMA (mma.sync bf16, 3-term split) GEMM ----------------
#define STAGE_BYTES 65536            // 4 arrays * 128 rows * 128 B
#define GEMM_SMEM_BYTES (1024 + 2 * STAGE_BYTES)

__device__ __forceinline__ uint32_t sw128(uint32_t r, uint32_t u) {
    return r * 128u + ((u ^ (r & 7u)) << 4);
}

// Output modes: Cf (fp32) | Cf16 (fp16) | Ch+Cl (bf16 pair).
// bnred: accumulate column sums/sumsq of stored values into g_bnsum/g_bnsq.
__global__ __launch_bounds__(256, 1)
void hmma_gemm(const __nv_bfloat16* __restrict__ Ah, const __nv_bfloat16* __restrict__ Al,
               const __nv_bfloat16* __restrict__ Bh, const __nv_bfloat16* __restrict__ Bl,
               const float* __restrict__ bias,
               float* __restrict__ Cf, __half* __restrict__ Cf16,
               __nv_bfloat16* __restrict__ Ch, __nv_bfloat16* __restrict__ Cl,
               int M, int Ntot, int K, int relu, int bnred,
               const float* __restrict__ resid, const float* __restrict__ eps_ptr)
{
    extern __shared__ char dsm[];
    uint32_t sb0 = smem_u32(dsm);
    uint32_t base0 = (sb0 + 1023u) & ~1023u;
    char* p0 = dsm + (base0 - sb0);   // generic pointer to aligned region

    int tid = threadIdx.x;
    int lane = tid & 31;
    int wid = tid >> 5;
    int wm = wid >> 2;
    int wn = wid & 3;
    int bm = blockIdx.y * 128, bn = blockIdx.x * 128;

    float acc[4][4][4];
#pragma unroll
    for (int i = 0; i < 4; i++)
#pragma unroll
        for (int j = 0; j < 4; j++)
#pragma unroll
            for (int k = 0; k < 4; k++) acc[i][j][k] = 0.f;

    const int NSt = K >> 6;

    const __nv_bfloat16* srcs[4] = { Ah, Al, Bh, Bl };
    const int rbase[4] = { bm, bm, bn, bn };
    const int rmax[4]  = { M - 1, M - 1, Ntot - 1, Ntot - 1 };

    auto load_stage = [&](int s) {
        uint32_t buf = base0 + (uint32_t)(s & 1) * STAGE_BYTES;
        int kc = s * 64;
#pragma unroll
        for (int t = 0; t < 4; t++) {
            const __nv_bfloat16* src = srcs[t];
            int rb = rbase[t], rm = rmax[t];
            uint32_t dbase = buf + t * 16384u;
#pragma unroll
            for (int i = 0; i < 4; i++) {
                int idx = tid + i * 256;
                uint32_t r = (uint32_t)(idx >> 3);
                uint32_t u = (uint32_t)(idx & 7);
                int gr = rb + (int)r; if (gr > rm) gr = rm;
                cpasync16(dbase + sw128(r, u), src + (size_t)gr * K + kc + u * 8);
            }
        }
        cp_commit();
    };

    load_stage(0);
    for (int s = 0; s < NSt; s++) {
        if (s + 1 < NSt) { load_stage(s + 1); cp_wait1(); }
        else cp_wait0();
        __syncthreads();

        uint32_t buf = base0 + (uint32_t)(s & 1) * STAGE_BYTES;
#pragma unroll
        for (int ks = 0; ks < 4; ks++) {
            uint32_t bh[4][2], bl[4][2];
#pragma unroll
            for (int jp = 0; jp < 2; jp++) {
                uint32_t n0 = (uint32_t)(wn * 32 + jp * 16);
                uint32_t r = n0 + (uint32_t)(lane & 7) + (uint32_t)((lane >> 4) << 3);
                uint32_t u = (uint32_t)(ks * 2 + ((lane >> 3) & 1));
                uint32_t off = sw128(r, u);
                uint32_t t4[4];
                ldsm4(t4, buf + 32768u + off);
                bh[jp * 2][0] = t4[0]; bh[jp * 2][1] = t4[1];
                bh[jp * 2 + 1][0] = t4[2]; bh[jp * 2 + 1][1] = t4[3];
                ldsm4(t4, buf + 49152u + off);
                bl[jp * 2][0] = t4[0]; bl[jp * 2][1] = t4[1];
                bl[jp * 2 + 1][0] = t4[2]; bl[jp * 2 + 1][1] = t4[3];
            }
#pragma unroll
            for (int mi = 0; mi < 4; mi++) {
                uint32_t m0 = (uint32_t)(wm * 64 + mi * 16);
                uint32_t r = m0 + (uint32_t)(lane & 15);
                uint32_t u = (uint32_t)(ks * 2 + (lane >> 4));
                uint32_t off = sw128(r, u);
                uint32_t ahf[4], alf[4];
                ldsm4(ahf, buf + off);
                ldsm4(alf, buf + 16384u + off);
#pragma unroll
                for (int ni = 0; ni < 4; ni++) {
                    mma_bf16(acc[mi][ni], ahf, bh[ni]);
                    mma_bf16(acc[mi][ni], ahf, bl[ni]);
                    mma_bf16(acc[mi][ni], alf, bh[ni]);
                }
            }
        }
        __syncthreads();
    }

    // ---------------- epilogue ----------------
    float e = resid ? __ldg(eps_ptr) : 0.f;
    float cs[4][2], cq[4][2];
#pragma unroll
    for (int ni = 0; ni < 4; ni++) { cs[ni][0] = cs[ni][1] = cq[ni][0] = cq[ni][1] = 0.f; }

#pragma unroll
    for (int mi = 0; mi < 4; mi++) {
#pragma unroll
        for (int rr = 0; rr < 2; rr++) {
            int gr = bm + wm * 64 + mi * 16 + (lane >> 2) + rr * 8;
            if (gr >= M) continue;
#pragma unroll
            for (int ni = 0; ni < 4; ni++) {
                int gc = bn + wn * 32 + ni * 8 + (lane & 3) * 2;
                float v0 = acc[mi][ni][rr * 2 + 0];
                float v1 = acc[mi][ni][rr * 2 + 1];
                float2 bv = *(const float2*)(bias + gc);
                v0 += bv.x; v1 += bv.y;
                if (resid) {
                    float2 rv = *(const float2*)(resid + (size_t)gr * Ntot + gc);
                    v0 += e * rv.x; v1 += e * rv.y;
                }
                if (relu) { v0 = fmaxf(v0, 0.f); v1 = fmaxf(v1, 0.f); }
                if (bnred) {
                    cs[ni][0] += v0; cq[ni][0] += v0 * v0;
                    cs[ni][1] += v1; cq[ni][1] += v1 * v1;
                }
                if (Cf) {
                    *(float2*)(Cf + (size_t)gr * Ntot + gc) = make_float2(v0, v1);
                } else if (Cf16) {
                    __half2 hv = __floats2half2_rn(v0, v1);
                    *(uint32_t*)(Cf16 + (size_t)gr * Ntot + gc) = *(uint32_t*)&hv;
                } else {
                    split_store2(Ch + (size_t)gr * Ntot + gc,
                                 Cl + (size_t)gr * Ntot + gc, v0, v1);
                }
            }
        }
    }

    if (bnred) {
        // reuse stage smem (free after last mainloop __syncthreads + register-only epilogue)
        float* bsum = (float*)p0;
        float* bsq  = bsum + 128;
        __syncthreads();
        if (tid < 256) ((float*)p0)[tid] = 0.f;
        __syncthreads();
#pragma unroll
        for (int ni = 0; ni < 4; ni++) {
#pragma unroll
            for (int h = 0; h < 2; h++) {
                int col = wn * 32 + ni * 8 + (lane & 3) * 2 + h;
                atomicAdd(&bsum[col], cs[ni][h]);
                atomicAdd(&bsq[col], cq[ni][h]);
            }
        }
        __syncthreads();
        if (tid < 128) {
            int gc = bn + tid;   // Ntot==128 for the BN GEMM
            atomicAdd(&g_bnsum[gc], bsum[tid]);
            atomicAdd(&g_bnsq[gc], bsq[tid]);
        }
    }
}

// ---------------- warp-per-node fp16 gather + segment sum/max (unroll 4) ----------------
__device__ __forceinline__ void acc_sum4(float4& s, uint2 u) {
    __half2 a = *(__half2*)&u.x, b = *(__half2*)&u.y;
    float2 f0 = __half22float2(a), f1 = __half22float2(b);
    s.x += f0.x; s.y += f0.y; s.z += f1.x; s.w += f1.y;
}
__device__ __forceinline__ void acc_max4(float4& m, uint2 u) {
    __half2 a = *(__half2*)&u.x, b = *(__half2*)&u.y;
    float2 f0 = __half22float2(a), f1 = __half22float2(b);
    m.x = fmaxf(m.x, f0.x); m.y = fmaxf(m.y, f0.y);
    m.z = fmaxf(m.z, f1.x); m.w = fmaxf(m.w, f1.y);
}

__global__ void gather_reduce_kernel(int n) {
    int gt = blockIdx.x * blockDim.x + threadIdx.x;
    int node = gt >> 5;
    if (node >= n) return;
    int lane = gt & 31;
    int start = g_rowstart[node];
    int deg = g_cnt[node];
    const __half* xf  = g_x_f16;
    const __half* xif = g_xi_f16;
    float4 s = make_float4(0.f, 0.f, 0.f, 0.f);
    float4 m = make_float4(-1e30f, -1e30f, -1e30f, -1e30f);
    int j = 0;
    for (; j + 4 <= deg; j += 4) {
        int nb0 = g_col[start + j],     nb1 = g_col[start + j + 1];
        int nb2 = g_col[start + j + 2], nb3 = g_col[start + j + 3];
        uint2 x0 = __ldg((const uint2*)(xf + (size_t)nb0 * 128 + lane * 4));
        uint2 x1 = __ldg((const uint2*)(xf + (size_t)nb1 * 128 + lane * 4));
        uint2 x2 = __ldg((const uint2*)(xf + (size_t)nb2 * 128 + lane * 4));
        uint2 x3 = __ldg((const uint2*)(xf + (size_t)nb3 * 128 + lane * 4));
        uint2 i0 = __ldg((const uint2*)(xif + (size_t)nb0 * 128 + lane * 4));
        uint2 i1 = __ldg((const uint2*)(xif + (size_t)nb1 * 128 + lane * 4));
        uint2 i2 = __ldg((const uint2*)(xif + (size_t)nb2 * 128 + lane * 4));
        uint2 i3 = __ldg((const uint2*)(xif + (size_t)nb3 * 128 + lane * 4));
        acc_sum4(s, x0); acc_sum4(s, x1); acc_sum4(s, x2); acc_sum4(s, x3);
        acc_max4(m, i0); acc_max4(m, i1); acc_max4(m, i2); acc_max4(m, i3);
    }
    for (; j < deg; j++) {
        int nb = g_col[start + j];
        uint2 xv = __ldg((const uint2*)(xf + (size_t)nb * 128 + lane * 4));
        uint2 iv = __ldg((const uint2*)(xif + (size_t)nb * 128 + lane * 4));
        acc_sum4(s, xv);
        acc_max4(m, iv);
    }
    if (deg == 0) m = make_float4(0.f, 0.f, 0.f, 0.f);
    split_store4(g_cat_h + (size_t)node * 256 + lane * 4,
                 g_cat_l + (size_t)node * 256 + lane * 4, s);
    split_store4(g_am_h + (size_t)node * 128 + lane * 4,
                 g_am_l + (size_t)node * 128 + lane * 4, m);
}

// ---------------- GRU cell elementwise ----------------
__device__ __forceinline__ float gru1(float ir, float hr, float iz, float hz,
                                      float inn, float hn, float xv) {
    float r = 1.f / (1.f + expf(-(ir + hr)));
    float z = 1.f / (1.f + expf(-(iz + hz)));
    float nc = tanhf(inn + r * hn);
    return (1.f - z) * nc + z * xv;
}

__global__ void gru_kernel(const float* __restrict__ x, int M) {
    int idx = blockIdx.x * blockDim.x + threadIdx.x;
    if (idx >= M * 32) return;
    int node = idx >> 5;
    int c = (idx & 31) * 4;
    const float* gi = g_gi + (size_t)node * 384;
    const float* gh = g_gh + (size_t)node * 384;
    float4 ir = *(const float4*)(gi + c);
    float4 iz = *(const float4*)(gi + 128 + c);
    float4 in = *(const float4*)(gi + 256 + c);
    float4 hr = *(const float4*)(gh + c);
    float4 hz = *(const float4*)(gh + 128 + c);
    float4 hn = *(const float4*)(gh + 256 + c);
    float4 xv = *(const float4*)(x + (size_t)node * 128 + c);
    float4 o;
    o.x = gru1(ir.x, hr.x, iz.x, hz.x, in.x, hn.x, xv.x);
    o.y = gru1(ir.y, hr.y, iz.y, hz.y, in.y, hn.y, xv.y);
    o.z = gru1(ir.z, hr.z, iz.z, hz.z, in.z, hn.z, xv.z);
    o.w = gru1(ir.w, hr.w, iz.w, hz.w, in.w, hn.w, xv.w);
    split_store4(g_cat_h + (size_t)node * 256 + 128 + c,
                 g_cat_l + (size_t)node * 256 + 128 + c, o);
}

// ---------------- batchnorm normalize ----------------
__global__ void bn_norm_kernel(float* __restrict__ out, const float* __restrict__ gamma,
                               const float* __restrict__ beta, int M, float invM) {
    int idx = blockIdx.x * blockDim.x + threadIdx.x;
    if (idx >= M * 32) return;
    int node = idx >> 5;
    int c = (idx & 31) * 4;
    float4 v = *(float4*)(out + (size_t)node * 128 + c);
    float4 sm = *(const float4*)(g_bnsum + c);
    float4 sq = *(const float4*)(g_bnsq + c);
    float4 gm = *(const float4*)(gamma + c);
    float4 bt = *(const float4*)(beta + c);
    float4 o;
    { float mean = sm.x * invM, var = sq.x * invM - mean * mean;
      o.x = gm.x * (v.x - mean) * rsqrtf(var + 1e-5f) + bt.x; }
    { float mean = sm.y * invM, var = sq.y * invM - mean * mean;
      o.y = gm.y * (v.y - mean) * rsqrtf(var + 1e-5f) + bt.y; }
    { float mean = sm.z * invM, var = sq.z * invM - mean * mean;
      o.z = gm.z * (v.z - mean) * rsqrtf(var + 1e-5f) + bt.z; }
    { float mean = sm.w * invM, var = sq.w * invM - mean * mean;
      o.w = gm.w * (v.w - mean) * rsqrtf(var + 1e-5f) + bt.w; }
    *(float4*)(out + (size_t)node * 128 + c) = o;
}

// ---------------- launch ----------------
extern "C" void kernel_launch(void* const* d_in, const int* in_sizes, int n_in,
                              void* d_out, int out_size) {
    const float* x       = (const float*)d_in[0];
    const int*   edges   = (const int*)d_in[1];
    const float* W_aff   = (const float*)d_in[2];
    const float* b_aff   = (const float*)d_in[3];
    const float* W_ih    = (const float*)d_in[4];
    const float* b_ih    = (const float*)d_in[5];
    const float* W_hh    = (const float*)d_in[6];
    const float* b_hh    = (const float*)d_in[7];
    const float* W_merge = (const float*)d_in[8];
    const float* b_merge = (const float*)d_in[9];
    const float* eps     = (const float*)d_in[10];
    const float* W1      = (const float*)d_in[11];
    const float* b1      = (const float*)d_in[12];
    const float* W2      = (const float*)d_in[13];
    const float* b2      = (const float*)d_in[14];
    const float* gamma   = (const float*)d_in[15];
    const float* beta    = (const float*)d_in[16];
    float* out = (float*)d_out;

    int M = in_sizes[0] / 128;
    int E = in_sizes[1] / 2;

    float *p_gh, *p_gi;
    __half *p_xf, *p_xif;
    __nv_bfloat16 *p_xh, *p_xl, *p_amh, *p_aml, *p_ch, *p_cl, *p_hh, *p_hl, *p_th, *p_tl, *p_wh, *p_wl;
    cudaGetSymbolAddress((void**)&p_gh, g_gh);
    cudaGetSymbolAddress((void**)&p_gi, g_gi);
    cudaGetSymbolAddress((void**)&p_xf, g_x_f16);
    cudaGetSymbolAddress((void**)&p_xif, g_xi_f16);
    cudaGetSymbolAddress((void**)&p_xh, g_x_h);
    cudaGetSymbolAddress((void**)&p_xl, g_x_l);
    cudaGetSymbolAddress((void**)&p_amh, g_am_h);
    cudaGetSymbolAddress((void**)&p_aml, g_am_l);
    cudaGetSymbolAddress((void**)&p_ch, g_cat_h);
    cudaGetSymbolAddress((void**)&p_cl, g_cat_l);
    cudaGetSymbolAddress((void**)&p_hh, g_hh_h);
    cudaGetSymbolAddress((void**)&p_hl, g_hh_l);
    cudaGetSymbolAddress((void**)&p_th, g_t_h);
    cudaGetSymbolAddress((void**)&p_tl, g_t_l);
    cudaGetSymbolAddress((void**)&p_wh, g_w_h);
    cudaGetSymbolAddress((void**)&p_wl, g_w_l);

    cudaFuncSetAttribute(hmma_gemm, cudaFuncAttributeMaxDynamicSharedMemorySize, GEMM_SMEM_BYTES);

    // one-time stream/event resources (host objects, not device memory)
    static cudaStream_t s1 = nullptr;
    static cudaEvent_t evR = nullptr, evCSR = nullptr, evXI = nullptr, evGH = nullptr;
    if (!s1) {
        cudaStreamCreateWithFlags(&s1, cudaStreamNonBlocking);
        cudaEventCreateWithFlags(&evR, cudaEventDisableTiming);
        cudaEventCreateWithFlags(&evCSR, cudaEventDisableTiming);
        cudaEventCreateWithFlags(&evXI, cudaEventDisableTiming);
        cudaEventCreateWithFlags(&evGH, cudaEventDisableTiming);
    }
    cudaStream_t s0 = 0;  // capture-origin (legacy default) stream

    int mb = (M + 127) / 128;
    int nb = (M + 1023) / 1024;

    // root: zero counters (CSR count + BN accumulators)
    zero_init_kernel<<<(M + 255) / 256, 256, 0, s0>>>(M);
    cudaEventRecord(evR, s0);

    // ---- branch s1: CSR build ----
    cudaStreamWaitEvent(s1, evR, 0);
    count_kernel<<<(E + 255) / 256, 256, 0, s1>>>(edges, E);
    scan1_kernel<<<nb, 1024, 0, s1>>>(M);
    scan2_kernel<<<1, 128, 0, s1>>>(nb);
    scan3_kernel<<<(M + 255) / 256, 256, 0, s1>>>(M);
    fill_kernel<<<(E + 255) / 256, 256, 0, s1>>>(edges, E);
    cudaEventRecord(evCSR, s1);

    // ---- main stream: splits + xi GEMM ----
    {
        int n4 = M * 128 / 4;
        split_kernel<<<(n4 + 255) / 256, 256, 0, s0>>>(x, p_xh, p_xl, p_xf, n4);
        split_weights_kernel<<<(53248 + 255) / 256, 256, 0, s0>>>(
            W_aff, W_ih, W_hh, W_merge, W1, W2, p_wh, p_wl);
    }
    // xi = x @ W_aff^T + b_aff -> fp16 (gather is the only consumer)
    hmma_gemm<<<dim3(1, mb), 256, GEMM_SMEM_BYTES, s0>>>(
        p_xh, p_xl, p_wh + OFF_AFF, p_wl + OFF_AFF, b_aff,
        nullptr, p_xif, nullptr, nullptr, M, 128, 128, 0, 0, nullptr, nullptr);
    cudaEventRecord(evXI, s0);

    // ---- branch s1: gh GEMM, concurrent with gather ----
    cudaStreamWaitEvent(s1, evXI, 0);
    hmma_gemm<<<dim3(3, mb), 256, GEMM_SMEM_BYTES, s1>>>(
        p_xh, p_xl, p_wh + OFF_HH, p_wl + OFF_HH, b_hh,
        p_gh, nullptr, nullptr, nullptr, M, 384, 128, 0, 0, nullptr, nullptr);
    cudaEventRecord(evGH, s1);

    // ---- main stream: gather (needs CSR + xi_f16 + x_f16) ----
    cudaStreamWaitEvent(s0, evCSR, 0);
    gather_reduce_kernel<<<(M * 32 + 255) / 256, 256, 0, s0>>>(M);

    // gi = agg_max @ W_ih^T + b_ih (fp32)
    hmma_gemm<<<dim3(3, mb), 256, GEMM_SMEM_BYTES, s0>>>(
        p_amh, p_aml, p_wh + OFF_IH, p_wl + OFF_IH, b_ih,
        p_gi, nullptr, nullptr, nullptr, M, 384, 128, 0, 0, nullptr, nullptr);

    // GRU (needs gi + gh) -> cat[:, 128:]
    cudaStreamWaitEvent(s0, evGH, 0);
    gru_kernel<<<(M * 32 + 255) / 256, 256, 0, s0>>>(x, M);

    // h = cat @ W_merge^T + b_merge + eps*x (bf16 pair)
    hmma_gemm<<<dim3(1, mb), 256, GEMM_SMEM_BYTES, s0>>>(
        p_ch, p_cl, p_wh + OFF_MG, p_wl + OFF_MG, b_merge,
        nullptr, nullptr, p_hh, p_hl, M, 128, 256, 0, 0, x, eps);

    // t = relu(h @ W1^T + b1) (bf16 pair)
    hmma_gemm<<<dim3(2, mb), 256, GEMM_SMEM_BYTES, s0>>>(
        p_hh, p_hl, p_wh + OFF_W1, p_wl + OFF_W1, b1,
        nullptr, nullptr, p_th, p_tl, M, 256, 128, 1, 0, nullptr, nullptr);

    // out = relu(t @ W2^T + b2) (fp32 -> d_out) + fused BN reduce
    hmma_gemm<<<dim3(1, mb), 256, GEMM_SMEM_BYTES, s0>>>(
        p_th, p_tl, p_wh + OFF_W2, p_wl + OFF_W2, b2,
        out, nullptr, nullptr, nullptr, M, 128, 256, 1, 1, nullptr, nullptr);

    // batchnorm normalize (train mode, biased variance)
    bn_norm_kernel<<<(M * 32 + 255) / 256, 256, 0, s0>>>(out, gamma, beta, M, 1.0f / (float)M);
}